// round 13
// baseline (speedup 1.0000x reference)
#include <cuda_runtime.h>
#include <cuda_bf16.h>
#include <cstdint>
#include <math.h>

// Problem constants
#define Bb   4
#define Nn   512
#define Dd   512
#define Hh   8
#define DHd  64
#define Kb   10
#define Mf   2048
#define Ll   4
#define TOK  (Bb*Nn)      // 2048
#define EPSf 1e-5f

// ---------------- scratch (device globals) ----------------------------------
__device__ float g_x[TOK*Dd];
__device__ unsigned char g_idx[Bb*Nn*Nn];
__device__ __nv_bfloat16 g_qkvhi[TOK*1536], g_qkvlo[TOK*1536];
__device__ __nv_bfloat16 g_hhi[TOK*Dd], g_hlo[TOK*Dd];
__device__ __nv_bfloat16 g_ohi[TOK*Dd], g_olo[TOK*Dd];
__device__ __nv_bfloat16 g_fhi[TOK*Mf], g_flo[TOK*Mf];
#define WL_STRIDE 3145728
__device__ __nv_bfloat16 g_whi[Ll*WL_STRIDE], g_wlo[Ll*WL_STRIDE];
__device__ float g_bqkv[Ll*1536];

// ---------------- helpers ----------------------------------------------------
__device__ __forceinline__ uint32_t smem_to_u32(const void* p) {
    uint32_t a;
    asm("{ .reg .u64 t; cvta.to.shared.u64 t, %1; cvt.u32.u64 %0, t; }"
        : "=r"(a) : "l"(p));
    return a;
}
__device__ __forceinline__ void cpa16(void* dst, const void* src) {
    uint32_t d = smem_to_u32(dst);
    asm volatile("cp.async.cg.shared.global [%0], [%1], 16;" :: "r"(d), "l"(src));
}
#define CP_COMMIT() asm volatile("cp.async.commit_group;" ::: "memory")
#define CP_WAIT(n)  asm volatile("cp.async.wait_group %0;" :: "n"(n) : "memory")

__device__ __forceinline__ void mma16816(float* c, const uint32_t* a, const uint32_t* b) {
    asm volatile("mma.sync.aligned.m16n8k16.row.col.f32.bf16.bf16.f32 "
        "{%0,%1,%2,%3}, {%4,%5,%6,%7}, {%8,%9}, {%0,%1,%2,%3};"
        : "+f"(c[0]), "+f"(c[1]), "+f"(c[2]), "+f"(c[3])
        : "r"(a[0]), "r"(a[1]), "r"(a[2]), "r"(a[3]), "r"(b[0]), "r"(b[1]));
}
__device__ __forceinline__ void ldm_x4(uint32_t* r, uint32_t addr) {
    asm volatile("ldmatrix.sync.aligned.m8n8.x4.shared.b16 {%0,%1,%2,%3}, [%4];"
        : "=r"(r[0]), "=r"(r[1]), "=r"(r[2]), "=r"(r[3]) : "r"(addr));
}
__device__ __forceinline__ void ldm_x4t(uint32_t* r, uint32_t addr) {
    asm volatile("ldmatrix.sync.aligned.m8n8.x4.trans.shared.b16 {%0,%1,%2,%3}, [%4];"
        : "=r"(r[0]), "=r"(r[1]), "=r"(r[2]), "=r"(r[3]) : "r"(addr));
}
__device__ __forceinline__ float bf2f(__nv_bfloat16 h) { return __bfloat162float(h); }

// FMA-pipe exp (rel err ~2e-6, x<=0)
__device__ __forceinline__ float fexp(float x) {
    float t = x * 1.4426950408889634f;
    float n = rintf(t);
    float f = t - n;
    float p = 1.3534581e-3f;
    p = fmaf(p, f, 9.6181291e-3f);
    p = fmaf(p, f, 5.5504109e-2f);
    p = fmaf(p, f, 2.4022651e-1f);
    p = fmaf(p, f, 6.9314718e-1f);
    p = fmaf(p, f, 1.0f);
    return p * __int_as_float(((int)n + 127) << 23);
}

// ---------------- distance bins (uint8) ----------------------------------------
__global__ void idx_kernel(const float* __restrict__ coord) {
    int n = blockIdx.x, b = blockIdx.y, m = threadIdx.x;
    float2 cn = ((const float2*)coord)[b*Nn + n];
    float2 cm = ((const float2*)coord)[b*Nn + m];
    float dx = cn.x - cm.x, dy = cn.y - cm.y;
    float dist = sqrtf(dx*dx + dy*dy);
    int j = (int)floorf(dist);
    j = j < 0 ? 0 : (j > Kb-1 ? Kb-1 : j);
    g_idx[((size_t)(b*Nn + n))*Nn + m] = (unsigned char)j;
}

// ---------------- ALL weight transposes+splits in ONE launch -------------------
__global__ void wconv_all_kernel(const float* __restrict__ wq, const float* __restrict__ wk,
                                 const float* __restrict__ wv, const float* __restrict__ wo,
                                 const float* __restrict__ w1, const float* __restrict__ w2) {
    __shared__ float t[32][33];
    int z = blockIdx.z, l = z / 6, job = z % 6;
    const float* W; int K, N; size_t off;
    switch (job) {
        case 0: W = wq + (size_t)l*Dd*Dd; K = 512;  N = 512;  off = 0;       break;
        case 1: W = wk + (size_t)l*Dd*Dd; K = 512;  N = 512;  off = 262144;  break;
        case 2: W = wv + (size_t)l*Dd*Dd; K = 512;  N = 512;  off = 524288;  break;
        case 3: W = wo + (size_t)l*Dd*Dd; K = 512;  N = 512;  off = 786432;  break;
        case 4: W = w1 + (size_t)l*Dd*Mf; K = 512;  N = 2048; off = 1048576; break;
        default:W = w2 + (size_t)l*Mf*Dd; K = 2048; N = 512;  off = 2097152; break;
    }
    __nv_bfloat16* dh = g_whi + (size_t)l*WL_STRIDE + off;
    __nv_bfloat16* dl = g_wlo + (size_t)l*WL_STRIDE + off;
    int reps = (job >= 4) ? 4 : 1;
    int tx = threadIdx.x, ty = threadIdx.y;
    for (int r = 0; r < reps; r++) {
        int nn0, k0;
        if (job == 4)      { nn0 = (blockIdx.x + 16*r)*32; k0 = blockIdx.y*32; }
        else if (job == 5) { nn0 = blockIdx.x*32; k0 = (blockIdx.y + 16*r)*32; }
        else               { nn0 = blockIdx.x*32; k0 = blockIdx.y*32; }
        #pragma unroll
        for (int i = 0; i < 4; i++)
            t[ty + i*8][tx] = W[(size_t)(k0 + ty + i*8)*N + nn0 + tx];
        __syncthreads();
        #pragma unroll
        for (int i = 0; i < 4; i++) {
            int nl = ty + i*8;
            float v = t[tx][nl];
            __nv_bfloat16 hb = __float2bfloat16_rn(v);
            size_t o = (size_t)(nn0 + nl)*K + k0 + tx;
            dh[o] = hb; dl[o] = __float2bfloat16_rn(v - bf2f(hb));
        }
        __syncthreads();
    }
}

__global__ void biaspack_kernel(const float* __restrict__ bq,
                                const float* __restrict__ bk,
                                const float* __restrict__ bv) {
    int i = blockIdx.x*256 + threadIdx.x;
    if (i >= Ll*1536) return;
    int l = i / 1536, c = i % 1536;
    g_bqkv[i] = (c < 512) ? bq[l*512 + c]
              : (c < 1024 ? bk[l*512 + c - 512] : bv[l*512 + c - 1024]);
}

// ---------------- layernorm: warp per row, 8 rows/block ------------------------
__global__ __launch_bounds__(256) void ln_kernel(
    const float* __restrict__ x, const float* __restrict__ g, const float* __restrict__ b,
    __nv_bfloat16* __restrict__ ohi, __nv_bfloat16* __restrict__ olo,
    float* __restrict__ of) {
    int wid = threadIdx.x >> 5, lane = threadIdx.x & 31;
    int row = blockIdx.x*8 + wid;
    const float* xr = x + (size_t)row*Dd;
    float4 v[4];
    float sum = 0.f;
    #pragma unroll
    for (int w = 0; w < 4; w++) {
        v[w] = *(const float4*)&xr[w*128 + lane*4];
        sum += v[w].x + v[w].y + v[w].z + v[w].w;
    }
    #pragma unroll
    for (int o = 16; o > 0; o >>= 1) sum += __shfl_xor_sync(~0u, sum, o);
    float mean = sum * (1.0f / Dd);
    float var = 0.f;
    #pragma unroll
    for (int w = 0; w < 4; w++) {
        v[w].x -= mean; v[w].y -= mean; v[w].z -= mean; v[w].w -= mean;
        var += v[w].x*v[w].x + v[w].y*v[w].y + v[w].z*v[w].z + v[w].w*v[w].w;
    }
    #pragma unroll
    for (int o = 16; o > 0; o >>= 1) var += __shfl_xor_sync(~0u, var, o);
    float inv = rsqrtf(var * (1.0f / Dd) + EPSf);
    #pragma unroll
    for (int w = 0; w < 4; w++) {
        int idx = w*128 + lane*4;
        float4 gg = *(const float4*)&g[idx];
        float4 bb = *(const float4*)&b[idx];
        float y0 = v[w].x*inv*gg.x + bb.x, y1 = v[w].y*inv*gg.y + bb.y;
        float y2 = v[w].z*inv*gg.z + bb.z, y3 = v[w].w*inv*gg.w + bb.w;
        if (of) {
            float4 o4 = {y0, y1, y2, y3};
            *(float4*)&of[(size_t)row*Dd + idx] = o4;
        } else {
            __nv_bfloat16 h0 = __float2bfloat16_rn(y0), h1 = __float2bfloat16_rn(y1);
            __nv_bfloat16 h2 = __float2bfloat16_rn(y2), h3 = __float2bfloat16_rn(y3);
            __nv_bfloat162 hp0(h0, h1), hp1(h2, h3);
            __nv_bfloat162 lp0(__float2bfloat16_rn(y0 - bf2f(h0)), __float2bfloat16_rn(y1 - bf2f(h1)));
            __nv_bfloat162 lp1(__float2bfloat16_rn(y2 - bf2f(h2)), __float2bfloat16_rn(y3 - bf2f(h3)));
            uint2 uh = { *(uint32_t*)&hp0, *(uint32_t*)&hp1 };
            uint2 ul = { *(uint32_t*)&lp0, *(uint32_t*)&lp1 };
            *(uint2*)&ohi[(size_t)row*Dd + idx] = uh;
            *(uint2*)&olo[(size_t)row*Dd + idx] = ul;
        }
    }
}

// ---------------- fused attention: all-MMA scores + PV -------------------------
#define SCS 520
#define ASMEM_TOTAL 110080
__global__ __launch_bounds__(256, 2) void attn_kernel(const float* __restrict__ relk,
                                                      const float* __restrict__ relv) {
    extern __shared__ char smx[];
    __nv_bfloat16* khi = (__nv_bfloat16*)smx;
    __nv_bfloat16* klo = (__nv_bfloat16*)(smx + 18432);
    float* sc   = (float*)(smx + 36864);
    __nv_bfloat16* phh = (__nv_bfloat16*)(smx + 70144);
    __nv_bfloat16* pll = (__nv_bfloat16*)(smx + 86784);
    __nv_bfloat16* qhi = (__nv_bfloat16*)(smx + 103424);
    __nv_bfloat16* qlo = (__nv_bfloat16*)(smx + 105728);
    float* qrs  = (float*)(smx + 108032);
    float* pbin = (float*)(smx + 109056);

    const int tid = threadIdx.x, w = tid >> 5, lane = tid & 31;
    const int n0 = blockIdx.x*16, h = blockIdx.y, b = blockIdx.z;
    const size_t tokbase = (size_t)(b*Nn);

    {
        int tensor = tid >> 7, idx = tid & 127, r = idx >> 3, cg = idx & 7;
        const __nv_bfloat16* src = (tensor ? g_qkvlo : g_qkvhi)
            + (tokbase + n0 + r)*1536 + h*DHd + cg*8;
        __nv_bfloat16* dst = (tensor ? qlo : qhi) + r*72 + cg*8;
        *(uint4*)dst = *(const uint4*)src;
    }
    pbin[tid] = 0.f;
    for (int i = tid; i < 2048; i += 256) {
        int tensor = i >> 10, idx = i & 1023, r = idx >> 3, cg = idx & 7;
        const __nv_bfloat16* src = (tensor ? g_qkvlo : g_qkvhi)
            + (tokbase + r)*1536 + Dd + h*DHd + cg*8;
        __nv_bfloat16* dst = (tensor ? klo : khi) + r*72 + cg*8;
        cpa16(dst, src);
    }
    CP_COMMIT();
    __syncthreads();

    if (tid < 16*Kb) {
        int qi = tid / Kb, j = tid % Kb;
        float dot = 0.f;
        #pragma unroll
        for (int d = 0; d < DHd; d++)
            dot += (bf2f(qhi[qi*72 + d]) + bf2f(qlo[qi*72 + d])) * relk[j*64 + d];
        qrs[qi*16 + j] = dot;
    }

    const int which = lane >> 3, rowin = lane & 7;
    const uint32_t aoff = (((which & 1)*8 + rowin)*72 + (which >> 1)*8)*2;
    const uint32_t boff = ((w*16 + (which >> 1)*8 + rowin)*72 + (which & 1)*8)*2;
    const uint32_t uQhi = smem_to_u32(qhi), uQlo = smem_to_u32(qlo);
    const uint32_t uKhi = smem_to_u32(khi), uKlo = smem_to_u32(klo);
    const int g = lane >> 2, t2 = (lane & 3)*2;

    for (int mc = 0; mc < 4; mc++) {
        if (mc == 0) {
            CP_WAIT(0);
        } else {
            for (int i = tid; i < 2048; i += 256) {
                int tensor = i >> 10, idx = i & 1023, r = idx >> 3, cg = idx & 7;
                const __nv_bfloat16* src = (tensor ? g_qkvlo : g_qkvhi)
                    + (tokbase + mc*128 + r)*1536 + Dd + h*DHd + cg*8;
                __nv_bfloat16* dst = (tensor ? klo : khi) + r*72 + cg*8;
                *(uint4*)dst = *(const uint4*)src;
            }
        }
        __syncthreads();
        float acc[2][4] = {};
        #pragma unroll
        for (int ks = 0; ks < 4; ks++) {
            uint32_t qh4[4], ql4[4], kh4[4], kl4[4];
            ldm_x4(qh4, uQhi + aoff + ks*32);
            ldm_x4(ql4, uQlo + aoff + ks*32);
            ldm_x4(kh4, uKhi + boff + ks*32);
            ldm_x4(kl4, uKlo + boff + ks*32);
            #pragma unroll
            for (int j = 0; j < 2; j++) {
                mma16816(acc[j], qh4, &kh4[j*2]);
                mma16816(acc[j], qh4, &kl4[j*2]);
                mma16816(acc[j], ql4, &kh4[j*2]);
            }
        }
        #pragma unroll
        for (int j = 0; j < 2; j++) {
            int m = mc*128 + w*16 + j*8 + t2;
            const unsigned char* ir0 = g_idx + (tokbase + n0 + g)*Nn + m;
            const unsigned char* ir1 = g_idx + (tokbase + n0 + g + 8)*Nn + m;
            sc[g*SCS + m]       = (acc[j][0] + qrs[g*16 + ir0[0]]) * 0.125f;
            sc[g*SCS + m + 1]   = (acc[j][1] + qrs[g*16 + ir0[1]]) * 0.125f;
            sc[(g+8)*SCS + m]   = (acc[j][2] + qrs[(g+8)*16 + ir1[0]]) * 0.125f;
            sc[(g+8)*SCS + m+1] = (acc[j][3] + qrs[(g+8)*16 + ir1[1]]) * 0.125f;
        }
        __syncthreads();
    }

    for (int i = tid; i < 2048; i += 256) {
        int tensor = i >> 10, idx = i & 1023, r = idx >> 3, cg = idx & 7;
        const __nv_bfloat16* src = (tensor ? g_qkvlo : g_qkvhi)
            + (tokbase + r)*1536 + 2*Dd + h*DHd + cg*8;
        __nv_bfloat16* dst = (tensor ? klo : khi) + r*72 + cg*8;
        cpa16(dst, src);
    }
    CP_COMMIT();

    #pragma unroll
    for (int rr = 0; rr < 2; rr++) {
        int row = w*2 + rr;
        float mx = -1e30f;
        for (int m = lane; m < 512; m += 32) mx = fmaxf(mx, sc[row*SCS + m]);
        #pragma unroll
        for (int o = 16; o > 0; o >>= 1) mx = fmaxf(mx, __shfl_xor_sync(~0u, mx, o));
        float sum = 0.f;
        for (int m = lane; m < 512; m += 32) {
            float e = fexp(sc[row*SCS + m] - mx);
            sc[row*SCS + m] = e; sum += e;
        }
        #pragma unroll
        for (int o = 16; o > 0; o >>= 1) sum += __shfl_xor_sync(~0u, sum, o);
        float inv = 1.f / sum;
        float pb[Kb];
        #pragma unroll
        for (int j = 0; j < Kb; j++) pb[j] = 0.f;
        const unsigned char* ir = g_idx + (tokbase + n0 + row)*Nn;
        for (int m = lane; m < 512; m += 32) {
            float p = sc[row*SCS + m] * inv;
            __nv_bfloat16 ph = __float2bfloat16_rn(p);
            phh[row*SCS + m] = ph;
            pll[row*SCS + m] = __float2bfloat16_rn(p - bf2f(ph));
            int ji = ir[m];
            #pragma unroll
            for (int j = 0; j < Kb; j++) if (ji == j) pb[j] += p;
        }
        #pragma unroll
        for (int j = 0; j < Kb; j++) {
            float v = pb[j];
            #pragma unroll
            for (int o = 16; o > 0; o >>= 1) v += __shfl_xor_sync(~0u, v, o);
            if (lane == 0) pbin[row*16 + j] = v;
        }
    }

    const int n0w = (w & 3)*16, khalf = w >> 2;
    const uint32_t uPh = smem_to_u32(phh), uPl = smem_to_u32(pll);
    const uint32_t paoff = (((which & 1)*8 + rowin)*SCS + (which >> 1)*8)*2;
    const uint32_t pboff = (((which & 1)*8 + rowin)*72 + n0w + (which >> 1)*8)*2;
    float c0[4] = {}, c1[4] = {};
    for (int mc = 0; mc < 4; mc++) {
        if (mc == 0) {
            CP_WAIT(0);
        } else {
            for (int i = tid; i < 2048; i += 256) {
                int tensor = i >> 10, idx = i & 1023, r = idx >> 3, cg = idx & 7;
                const __nv_bfloat16* src = (tensor ? g_qkvlo : g_qkvhi)
                    + (tokbase + mc*128 + r)*1536 + 2*Dd + h*DHd + cg*8;
                __nv_bfloat16* dst = (tensor ? klo : khi) + r*72 + cg*8;
                *(uint4*)dst = *(const uint4*)src;
            }
        }
        __syncthreads();
        #pragma unroll
        for (int ks = 0; ks < 4; ks++) {
            int kP = mc*128 + khalf*64 + ks*16;
            int kV = khalf*64 + ks*16;
            uint32_t ph4[4], pl4[4], vh4[4], vl4[4];
            ldm_x4(ph4, uPh + paoff + kP*2);
            ldm_x4(pl4, uPl + paoff + kP*2);
            ldm_x4t(vh4, uKhi + pboff + kV*144);
            ldm_x4t(vl4, uKlo + pboff + kV*144);
            mma16816(c0, ph4, &vh4[0]);
            mma16816(c0, ph4, &vl4[0]);
            mma16816(c0, pl4, &vh4[0]);
            mma16816(c1, ph4, &vh4[2]);
            mma16816(c1, ph4, &vl4[2]);
            mma16816(c1, pl4, &vh4[2]);
        }
        __syncthreads();
    }
    {
        float* outp = sc + khalf*(16*68);
        outp[g*68 + n0w + t2]          = c0[0];
        outp[g*68 + n0w + t2 + 1]      = c0[1];
        outp[(g+8)*68 + n0w + t2]      = c0[2];
        outp[(g+8)*68 + n0w + t2 + 1]  = c0[3];
        outp[g*68 + n0w + 8 + t2]      = c1[0];
        outp[g*68 + n0w + 8 + t2 + 1]  = c1[1];
        outp[(g+8)*68 + n0w + 8 + t2]  = c1[2];
        outp[(g+8)*68 + n0w + 8 + t2+1]= c1[3];
    }
    __syncthreads();
    for (int i = tid; i < 1024; i += 256) {
        int qi = i >> 6, d = i & 63;
        float o = sc[qi*68 + d] + sc[16*68 + qi*68 + d];
        #pragma unroll
        for (int j = 0; j < Kb; j++) o += pbin[qi*16 + j] * relv[j*64 + d];
        size_t tok = tokbase + n0 + qi;
        __nv_bfloat16 hb = __float2bfloat16_rn(o);
        g_ohi[tok*Dd + h*DHd + d] = hb;
        g_olo[tok*Dd + h*DHd + d] = __float2bfloat16_rn(o - bf2f(hb));
    }
}

// ---------------- GEMM v2: CTA 128x128, warp 32x64 (4:1 MMA:ldm), 3-stage -----
// 256 thr, 8 warps (4m x 2n). Output bf16 hi/lo (+gelu). 1 CTA/SM (122KB smem).
#define SSTR 40
#define G2SMEM 122880
__global__ __launch_bounds__(256) void gemm_mma2_kernel(
    const __nv_bfloat16* __restrict__ Ahi, const __nv_bfloat16* __restrict__ Alo,
    const __nv_bfloat16* __restrict__ Bhi, const __nv_bfloat16* __restrict__ Blo,
    const float* __restrict__ bias,
    __nv_bfloat16* __restrict__ Chi, __nv_bfloat16* __restrict__ Clo,
    int Nc, int Kc, int doGelu) {
    extern __shared__ char smx[];
    __nv_bfloat16* sAhi = (__nv_bfloat16*)smx;            // [3][128*SSTR]
    __nv_bfloat16* sAlo = sAhi + 3*128*SSTR;
    __nv_bfloat16* sBhi = sAlo + 3*128*SSTR;
    __nv_bfloat16* sBlo = sBhi + 3*128*SSTR;

    const int tid = threadIdx.x, wid = tid >> 5, lane = tid & 31;
    const int g = lane >> 2, t2 = (lane & 3)*2;
    const int wm = (wid & 3)*32, wn = (wid >> 2)*64;
    const int m0 = blockIdx.y*128, n0 = blockIdx.x*128;

    const int which = lane >> 3, rowin = lane & 7;
    uint32_t aoff[2], boff[4];
    #pragma unroll
    for (int i = 0; i < 2; i++)
        aoff[i] = ((wm + i*16 + (which & 1)*8 + rowin)*SSTR + (which >> 1)*8)*2;
    #pragma unroll
    for (int p = 0; p < 4; p++)
        boff[p] = ((wn + p*16 + (which >> 1)*8 + rowin)*SSTR + (which & 1)*8)*2;
    const uint32_t uAhi = smem_to_u32(sAhi), uAlo = smem_to_u32(sAlo);
    const uint32_t uBhi = smem_to_u32(sBhi), uBlo = smem_to_u32(sBlo);

    auto issue = [&](int c, int buf) {
        int kc = c*32;
        #pragma unroll
        for (int it = 0; it < 2; it++) {
            int idx = tid + it*256;
            int r = idx >> 2, cc = (idx & 3)*8;
            cpa16(&sAhi[buf*(128*SSTR) + r*SSTR + cc], Ahi + (size_t)(m0 + r)*Kc + kc + cc);
            cpa16(&sAlo[buf*(128*SSTR) + r*SSTR + cc], Alo + (size_t)(m0 + r)*Kc + kc + cc);
            cpa16(&sBhi[buf*(128*SSTR) + r*SSTR + cc], Bhi + (size_t)(n0 + r)*Kc + kc + cc);
            cpa16(&sBlo[buf*(128*SSTR) + r*SSTR + cc], Blo + (size_t)(n0 + r)*Kc + kc + cc);
        }
    };

    float acc[2][8][4] = {};
    const int nch = Kc >> 5;
    issue(0, 0); CP_COMMIT();
    issue(1, 1); CP_COMMIT();

    for (int c = 0; c < nch; c++) {
        int buf = c % 3;
        if (c + 2 < nch) {
            CP_WAIT(1);
            __syncthreads();
            issue(c + 2, (c + 2) % 3);
            CP_COMMIT();
        } else {
            CP_WAIT(0);
            __syncthreads();
        }
        const uint32_t offA = buf*(128*SSTR*2), offB = buf*(128*SSTR*2);
        #pragma unroll
        for (int ks = 0; ks < 32; ks += 16) {
            uint32_t ah[2][4], al[2][4];
            #pragma unroll
            for (int i = 0; i < 2; i++) {
                ldm_x4(ah[i], uAhi + offA + aoff[i] + ks*2);
                ldm_x4(al[i], uAlo + offA + aoff[i] + ks*2);
            }
            #pragma unroll
            for (int p = 0; p < 4; p++) {
                uint32_t bh4[4], bl4[4];
                ldm_x4(bh4, uBhi + offB + boff[p] + ks*2);
                ldm_x4(bl4, uBlo + offB + boff[p] + ks*2);
                #pragma unroll
                for (int i = 0; i < 2; i++) {
                    mma16816(acc[i][2*p],   ah[i], &bh4[0]);
                    mma16816(acc[i][2*p],   ah[i], &bl4[0]);
                    mma16816(acc[i][2*p],   al[i], &bh4[0]);
                    mma16816(acc[i][2*p+1], ah[i], &bh4[2]);
                    mma16816(acc[i][2*p+1], ah[i], &bl4[2]);
                    mma16816(acc[i][2*p+1], al[i], &bh4[2]);
                }
            }
        }
    }

    #pragma unroll
    for (int i = 0; i < 2; i++) {
        int r0 = m0 + wm + i*16 + g;
        #pragma unroll
        for (int jj = 0; jj < 8; jj++) {
            int col = n0 + wn + jj*8 + t2;
            float b0 = bias[col], b1 = bias[col + 1];
            float2 v0 = { acc[i][jj][0] + b0, acc[i][jj][1] + b1 };
            float2 v1 = { acc[i][jj][2] + b0, acc[i][jj][3] + b1 };
            if (doGelu) {
                v0.x = 0.5f*v0.x*(1.f + erff(v0.x*0.70710678118654752f));
                v0.y = 0.5f*v0.y*(1.f + erff(v0.y*0.70710678118654752f));
                v1.x = 0.5f*v1.x*(1.f + erff(v1.x*0.70710678118654752f));
                v1.y = 0.5f*v1.y*(1.f + erff(v1.y*0.70710678118654752f));
            }
            __nv_bfloat16 h00 = __float2bfloat16_rn(v0.x), h01 = __float2bfloat16_rn(v0.y);
            __nv_bfloat16 h10 = __float2bfloat16_rn(v1.x), h11 = __float2bfloat16_rn(v1.y);
            __nv_bfloat162 hp0(h00, h01), hp1(h10, h11);
            __nv_bfloat162 lp0(__float2bfloat16_rn(v0.x - bf2f(h00)), __float2bfloat16_rn(v0.y - bf2f(h01)));
            __nv_bfloat162 lp1(__float2bfloat16_rn(v1.x - bf2f(h10)), __float2bfloat16_rn(v1.y - bf2f(h11)));
            *(uint32_t*)&Chi[(size_t)r0*Nc + col]       = *(uint32_t*)&hp0;
            *(uint32_t*)&Chi[(size_t)(r0 + 8)*Nc + col] = *(uint32_t*)&hp1;
            *(uint32_t*)&Clo[(size_t)r0*Nc + col]       = *(uint32_t*)&lp0;
            *(uint32_t*)&Clo[(size_t)(r0 + 8)*Nc + col] = *(uint32_t*)&lp1;
        }
    }
}

// ---------------- GEMM v1: CTA 64x128 (residual/fp32-out path, WO/FF2) --------
#define GSMEM_TOTAL 92160
__global__ __launch_bounds__(256, 2) void gemm_mma_kernel(
    const __nv_bfloat16* __restrict__ Ahi, const __nv_bfloat16* __restrict__ Alo,
    const __nv_bfloat16* __restrict__ Bhi, const __nv_bfloat16* __restrict__ Blo,
    const float* __restrict__ bias, const float* __restrict__ res,
    float* __restrict__ Cf, int Nc, int Kc) {
    extern __shared__ char smx[];
    __nv_bfloat16* sAhi = (__nv_bfloat16*)smx;
    __nv_bfloat16* sAlo = sAhi + 3*64*SSTR;
    __nv_bfloat16* sBhi = sAlo + 3*64*SSTR;
    __nv_bfloat16* sBlo = sBhi + 3*128*SSTR;

    const int tid = threadIdx.x, wid = tid >> 5, lane = tid & 31;
    const int g = lane >> 2, t2 = (lane & 3)*2;
    const int wm = (wid >> 2)*32, wn = (wid & 3)*32;
    const int m0 = blockIdx.y*64, n0 = blockIdx.x*128;

    const int ar = tid >> 2, ac = (tid & 3)*8;
    const int br0 = tid >> 2, bc0 = (tid & 3)*8;
    const int br1 = (tid + 256) >> 2, bc1 = ((tid + 256) & 3)*8;

    const int which = lane >> 3, rowin = lane & 7;
    uint32_t aoff[2], boff[2];
    #pragma unroll
    for (int i = 0; i < 2; i++)
        aoff[i] = ((wm + i*16 + (which & 1)*8 + rowin)*SSTR + (which >> 1)*8)*2;
    #pragma unroll
    for (int p = 0; p < 2; p++)
        boff[p] = ((wn + p*16 + (which >> 1)*8 + rowin)*SSTR + (which & 1)*8)*2;
    const uint32_t uAhi = smem_to_u32(sAhi), uAlo = smem_to_u32(sAlo);
    const uint32_t uBhi = smem_to_u32(sBhi), uBlo = smem_to_u32(sBlo);

    auto issue = [&](int c, int buf) {
        int kc = c*32;
        cpa16(&sAhi[buf*(64*SSTR) + ar*SSTR + ac], Ahi + (size_t)(m0 + ar)*Kc + kc + ac);
        cpa16(&sAlo[buf*(64*SSTR) + ar*SSTR + ac], Alo + (size_t)(m0 + ar)*Kc + kc + ac);
        cpa16(&sBhi[buf*(128*SSTR) + br0*SSTR + bc0], Bhi + (size_t)(n0 + br0)*Kc + kc + bc0);
        cpa16(&sBhi[buf*(128*SSTR) + br1*SSTR + bc1], Bhi + (size_t)(n0 + br1)*Kc + kc + bc1);
        cpa16(&sBlo[buf*(128*SSTR) + br0*SSTR + bc0], Blo + (size_t)(n0 + br0)*Kc + kc + bc0);
        cpa16(&sBlo[buf*(128*SSTR) + br1*SSTR + bc1], Blo + (size_t)(n0 + br1)*Kc + kc + bc1);
    };

    float acc[2][4][4] = {};
    const int nch = Kc >> 5;
    issue(0, 0); CP_COMMIT();
    issue(1, 1); CP_COMMIT();

    for (int c = 0; c < nch; c++) {
        int buf = c % 3;
        if (c + 2 < nch) {
            CP_WAIT(1);
            __syncthreads();
            issue(c + 2, (c + 2) % 3);
            CP_COMMIT();
        } else {
            CP_WAIT(0);
            __syncthreads();
        }
        const uint32_t offA = buf*(64*SSTR*2), offB = buf*(128*SSTR*2);
        #pragma unroll
        for (int ks = 0; ks < 32; ks += 16) {
            uint32_t ah[2][4], al[2][4], bh[8], bl[8];
            #pragma unroll
            for (int i = 0; i < 2; i++) {
                ldm_x4(ah[i], uAhi + offA + aoff[i] + ks*2);
                ldm_x4(al[i], uAlo + offA + aoff[i] + ks*2);
            }
            #pragma unroll
            for (int p = 0; p < 2; p++) {
                ldm_x4(&bh[p*4], uBhi + offB + boff[p] + ks*2);
                ldm_x4(&bl[p*4], uBlo + offB + boff[p] + ks*2);
            }
            #pragma unroll
            for (int i = 0; i < 2; i++)
                #pragma unroll
                for (int j = 0; j < 4; j++) {
                    mma16816(acc[i][j], ah[i], &bh[j*2]);
                    mma16816(acc[i][j], ah[i], &bl[j*2]);
                    mma16816(acc[i][j], al[i], &bh[j*2]);
                }
        }
    }

    #pragma unroll
    for (int i = 0; i < 2; i++) {
        int r0 = m0 + wm + i*16 + g;
        #pragma unroll
        for (int j = 0; j < 4; j++) {
            int col = n0 + wn + j*8 + t2;
            float b0 = bias[col], b1 = bias[col + 1];
            float2 v0 = { acc[i][j][0] + b0, acc[i][j][1] + b1 };
            float2 v1 = { acc[i][j][2] + b0, acc[i][j][3] + b1 };
            float2 r0v = *(const float2*)&res[(size_t)r0*Nc + col];
            float2 r1v = *(const float2*)&res[(size_t)(r0 + 8)*Nc + col];
            v0.x += r0v.x; v0.y += r0v.y; v1.x += r1v.x; v1.y += r1v.y;
            *(float2*)&Cf[(size_t)r0*Nc + col]       = v0;
            *(float2*)&Cf[(size_t)(r0 + 8)*Nc + col] = v1;
        }
    }
}

// ---------------------------------------------------------------------------
extern "C" void kernel_launch(void* const* d_in, const int* in_sizes, int n_in,
                              void* d_out, int out_size) {
    const float* x     = (const float*)d_in[0];
    const float* coord = (const float*)d_in[1];
    const float* ln1_g = (const float*)d_in[2];
    const float* ln1_b = (const float*)d_in[3];
    const float* wq    = (const float*)d_in[4];
    const float* bq    = (const float*)d_in[5];
    const float* wk    = (const float*)d_in[6];
    const float* bk    = (const float*)d_in[7];
    const float* wv    = (const float*)d_in[8];
    const float* bv    = (const float*)d_in[9];
    const float* wo    = (const float*)d_in[10];
    const float* bo    = (const float*)d_in[11];
    const float* rel_k = (const float*)d_in[12];
    const float* rel_v = (const float*)d_in[13];
    const float* ln2_g = (const float*)d_in[14];
    const float* ln2_b = (const float*)d_in[15];
    const float* w1    = (const float*)d_in[16];
    const float* b1    = (const float*)d_in[17];
    const float* w2    = (const float*)d_in[18];
    const float* b2    = (const float*)d_in[19];
    const float* lnf_g = (const float*)d_in[20];
    const float* lnf_b = (const float*)d_in[21];

    float *px, *pbqkv;
    __nv_bfloat16 *pqkvhi, *pqkvlo, *phhi, *phlo, *pohi, *polo, *pfhi, *pflo, *pwhi, *pwlo;
    cudaGetSymbolAddress((void**)&px,     g_x);
    cudaGetSymbolAddress((void**)&pbqkv,  g_bqkv);
    cudaGetSymbolAddress((void**)&pqkvhi, g_qkvhi);
    cudaGetSymbolAddress((void**)&pqkvlo, g_qkvlo);
    cudaGetSymbolAddress((void**)&phhi,   g_hhi);
    cudaGetSymbolAddress((void**)&phlo,   g_hlo);
    cudaGetSymbolAddress((void**)&pohi,   g_ohi);
    cudaGetSymbolAddress((void**)&polo,   g_olo);
    cudaGetSymbolAddress((void**)&pfhi,   g_fhi);
    cudaGetSymbolAddress((void**)&pflo,   g_flo);
    cudaGetSymbolAddress((void**)&pwhi,   g_whi);
    cudaGetSymbolAddress((void**)&pwlo,   g_wlo);

    cudaFuncSetAttribute(gemm_mma_kernel, cudaFuncAttributeMaxDynamicSharedMemorySize, GSMEM_TOTAL);
    cudaFuncSetAttribute(gemm_mma2_kernel, cudaFuncAttributeMaxDynamicSharedMemorySize, G2SMEM);
    cudaFuncSetAttribute(attn_kernel, cudaFuncAttributeMaxDynamicSharedMemorySize, ASMEM_TOTAL);

    // Order keeps ncu capture window on the layer-0 QKV GEMM (v2).
    cudaMemcpyAsync(px, x, sizeof(float)*TOK*Dd, cudaMemcpyDeviceToDevice);
    biaspack_kernel<<<(Ll*1536 + 255)/256, 256>>>(bq, bk, bv);
    wconv_all_kernel<<<dim3(16, 16, Ll*6), dim3(32, 8)>>>(wq, wk, wv, wo, w1, w2);

    const dim3 gQKV(12, 16);   // 128x128 tiles, N=1536 -> 192 CTAs
    const dim3 gFF1(16, 16);   // 128x128 tiles, N=2048 -> 256 CTAs
    const dim3 gPRJ(4, 32);    // 64x128 tiles,  N=512  -> 128 CTAs

    for (int l = 0; l < Ll; l++) {
        size_t lo = (size_t)l * WL_STRIDE;
        ln_kernel<<<TOK/8, 256>>>(px, ln1_g + l*Dd, ln1_b + l*Dd, phhi, phlo, nullptr);
        gemm_mma2_kernel<<<gQKV, 256, G2SMEM>>>(
            phhi, phlo, pwhi + lo, pwlo + lo, pbqkv + l*1536,
            pqkvhi, pqkvlo, 1536, 512, 0);
        if (l == 0) idx_kernel<<<dim3(Nn, Bb), Nn>>>(coord);
        attn_kernel<<<dim3(Nn/16, Hh, Bb), 256, ASMEM_TOTAL>>>(
            rel_k + (size_t)l*Kb*DHd, rel_v + (size_t)l*Kb*DHd);
        gemm_mma_kernel<<<gPRJ, 256, GSMEM_TOTAL>>>(
            pohi, polo, pwhi + lo + 786432, pwlo + lo + 786432, bo + l*Dd, px,
            px, 512, 512);
        ln_kernel<<<TOK/8, 256>>>(px, ln2_g + l*Dd, ln2_b + l*Dd, phhi, phlo, nullptr);
        gemm_mma2_kernel<<<gFF1, 256, G2SMEM>>>(
            phhi, phlo, pwhi + lo + 1048576, pwlo + lo + 1048576, b1 + l*Mf,
            pfhi, pflo, 2048, 512, 1);
        gemm_mma_kernel<<<gPRJ, 256, GSMEM_TOTAL>>>(
            pfhi, pflo, pwhi + lo + 2097152, pwlo + lo + 2097152, b2 + l*Dd, px,
            px, 512, 2048);
    }
    ln_kernel<<<TOK/8, 256>>>(px, lnf_g, lnf_b, nullptr, nullptr, (float*)d_out);
}

// round 14
// speedup vs baseline: 1.0294x; 1.0294x over previous
#include <cuda_runtime.h>
#include <cuda_bf16.h>
#include <cstdint>
#include <math.h>

// Problem constants
#define Bb   4
#define Nn   512
#define Dd   512
#define Hh   8
#define DHd  64
#define Kb   10
#define Mf   2048
#define Ll   4
#define TOK  (Bb*Nn)      // 2048
#define EPSf 1e-5f

// ---------------- scratch (device globals) ----------------------------------
__device__ float g_x[TOK*Dd];
__device__ unsigned char g_idx[Bb*Nn*Nn];
__device__ __nv_bfloat16 g_qkvhi[TOK*1536], g_qkvlo[TOK*1536];
__device__ __nv_bfloat16 g_hhi[TOK*Dd], g_hlo[TOK*Dd];
__device__ __nv_bfloat16 g_ohi[TOK*Dd], g_olo[TOK*Dd];
__device__ __nv_bfloat16 g_fhi[TOK*Mf], g_flo[TOK*Mf];
#define WL_STRIDE 3145728
__device__ __nv_bfloat16 g_whi[Ll*WL_STRIDE], g_wlo[Ll*WL_STRIDE];
__device__ float g_bqkv[Ll*1536];

// ---------------- helpers ----------------------------------------------------
__device__ __forceinline__ uint32_t smem_to_u32(const void* p) {
    uint32_t a;
    asm("{ .reg .u64 t; cvta.to.shared.u64 t, %1; cvt.u32.u64 %0, t; }"
        : "=r"(a) : "l"(p));
    return a;
}
__device__ __forceinline__ void cpa16(void* dst, const void* src) {
    uint32_t d = smem_to_u32(dst);
    asm volatile("cp.async.cg.shared.global [%0], [%1], 16;" :: "r"(d), "l"(src));
}
#define CP_COMMIT() asm volatile("cp.async.commit_group;" ::: "memory")
#define CP_WAIT(n)  asm volatile("cp.async.wait_group %0;" :: "n"(n) : "memory")

__device__ __forceinline__ void mma16816(float* c, const uint32_t* a, const uint32_t* b) {
    asm volatile("mma.sync.aligned.m16n8k16.row.col.f32.bf16.bf16.f32 "
        "{%0,%1,%2,%3}, {%4,%5,%6,%7}, {%8,%9}, {%0,%1,%2,%3};"
        : "+f"(c[0]), "+f"(c[1]), "+f"(c[2]), "+f"(c[3])
        : "r"(a[0]), "r"(a[1]), "r"(a[2]), "r"(a[3]), "r"(b[0]), "r"(b[1]));
}
__device__ __forceinline__ void ldm_x4(uint32_t* r, uint32_t addr) {
    asm volatile("ldmatrix.sync.aligned.m8n8.x4.shared.b16 {%0,%1,%2,%3}, [%4];"
        : "=r"(r[0]), "=r"(r[1]), "=r"(r[2]), "=r"(r[3]) : "r"(addr));
}
__device__ __forceinline__ void ldm_x4t(uint32_t* r, uint32_t addr) {
    asm volatile("ldmatrix.sync.aligned.m8n8.x4.trans.shared.b16 {%0,%1,%2,%3}, [%4];"
        : "=r"(r[0]), "=r"(r[1]), "=r"(r[2]), "=r"(r[3]) : "r"(addr));
}
__device__ __forceinline__ float bf2f(__nv_bfloat16 h) { return __bfloat162float(h); }

// FMA-pipe exp (rel err ~2e-6, x<=0)
__device__ __forceinline__ float fexp(float x) {
    float t = x * 1.4426950408889634f;
    float n = rintf(t);
    float f = t - n;
    float p = 1.3534581e-3f;
    p = fmaf(p, f, 9.6181291e-3f);
    p = fmaf(p, f, 5.5504109e-2f);
    p = fmaf(p, f, 2.4022651e-1f);
    p = fmaf(p, f, 6.9314718e-1f);
    p = fmaf(p, f, 1.0f);
    return p * __int_as_float(((int)n + 127) << 23);
}

// ---------------- distance bins (uint8) ----------------------------------------
__global__ void idx_kernel(const float* __restrict__ coord) {
    int n = blockIdx.x, b = blockIdx.y, m = threadIdx.x;
    float2 cn = ((const float2*)coord)[b*Nn + n];
    float2 cm = ((const float2*)coord)[b*Nn + m];
    float dx = cn.x - cm.x, dy = cn.y - cm.y;
    float dist = sqrtf(dx*dx + dy*dy);
    int j = (int)floorf(dist);
    j = j < 0 ? 0 : (j > Kb-1 ? Kb-1 : j);
    g_idx[((size_t)(b*Nn + n))*Nn + m] = (unsigned char)j;
}

// ---------------- ALL weight transposes+splits in ONE launch -------------------
__global__ void wconv_all_kernel(const float* __restrict__ wq, const float* __restrict__ wk,
                                 const float* __restrict__ wv, const float* __restrict__ wo,
                                 const float* __restrict__ w1, const float* __restrict__ w2) {
    __shared__ float t[32][33];
    int z = blockIdx.z, l = z / 6, job = z % 6;
    const float* W; int K, N; size_t off;
    switch (job) {
        case 0: W = wq + (size_t)l*Dd*Dd; K = 512;  N = 512;  off = 0;       break;
        case 1: W = wk + (size_t)l*Dd*Dd; K = 512;  N = 512;  off = 262144;  break;
        case 2: W = wv + (size_t)l*Dd*Dd; K = 512;  N = 512;  off = 524288;  break;
        case 3: W = wo + (size_t)l*Dd*Dd; K = 512;  N = 512;  off = 786432;  break;
        case 4: W = w1 + (size_t)l*Dd*Mf; K = 512;  N = 2048; off = 1048576; break;
        default:W = w2 + (size_t)l*Mf*Dd; K = 2048; N = 512;  off = 2097152; break;
    }
    __nv_bfloat16* dh = g_whi + (size_t)l*WL_STRIDE + off;
    __nv_bfloat16* dl = g_wlo + (size_t)l*WL_STRIDE + off;
    int reps = (job >= 4) ? 4 : 1;
    int tx = threadIdx.x, ty = threadIdx.y;
    for (int r = 0; r < reps; r++) {
        int nn0, k0;
        if (job == 4)      { nn0 = (blockIdx.x + 16*r)*32; k0 = blockIdx.y*32; }
        else if (job == 5) { nn0 = blockIdx.x*32; k0 = (blockIdx.y + 16*r)*32; }
        else               { nn0 = blockIdx.x*32; k0 = blockIdx.y*32; }
        #pragma unroll
        for (int i = 0; i < 4; i++)
            t[ty + i*8][tx] = W[(size_t)(k0 + ty + i*8)*N + nn0 + tx];
        __syncthreads();
        #pragma unroll
        for (int i = 0; i < 4; i++) {
            int nl = ty + i*8;
            float v = t[tx][nl];
            __nv_bfloat16 hb = __float2bfloat16_rn(v);
            size_t o = (size_t)(nn0 + nl)*K + k0 + tx;
            dh[o] = hb; dl[o] = __float2bfloat16_rn(v - bf2f(hb));
        }
        __syncthreads();
    }
}

__global__ void biaspack_kernel(const float* __restrict__ bq,
                                const float* __restrict__ bk,
                                const float* __restrict__ bv) {
    int i = blockIdx.x*256 + threadIdx.x;
    if (i >= Ll*1536) return;
    int l = i / 1536, c = i % 1536;
    g_bqkv[i] = (c < 512) ? bq[l*512 + c]
              : (c < 1024 ? bk[l*512 + c - 512] : bv[l*512 + c - 1024]);
}

// ---------------- layernorm: warp per row, 8 rows/block ------------------------
__global__ __launch_bounds__(256) void ln_kernel(
    const float* __restrict__ x, const float* __restrict__ g, const float* __restrict__ b,
    __nv_bfloat16* __restrict__ ohi, __nv_bfloat16* __restrict__ olo,
    float* __restrict__ of) {
    int wid = threadIdx.x >> 5, lane = threadIdx.x & 31;
    int row = blockIdx.x*8 + wid;
    const float* xr = x + (size_t)row*Dd;
    float4 v[4];
    float sum = 0.f;
    #pragma unroll
    for (int w = 0; w < 4; w++) {
        v[w] = *(const float4*)&xr[w*128 + lane*4];
        sum += v[w].x + v[w].y + v[w].z + v[w].w;
    }
    #pragma unroll
    for (int o = 16; o > 0; o >>= 1) sum += __shfl_xor_sync(~0u, sum, o);
    float mean = sum * (1.0f / Dd);
    float var = 0.f;
    #pragma unroll
    for (int w = 0; w < 4; w++) {
        v[w].x -= mean; v[w].y -= mean; v[w].z -= mean; v[w].w -= mean;
        var += v[w].x*v[w].x + v[w].y*v[w].y + v[w].z*v[w].z + v[w].w*v[w].w;
    }
    #pragma unroll
    for (int o = 16; o > 0; o >>= 1) var += __shfl_xor_sync(~0u, var, o);
    float inv = rsqrtf(var * (1.0f / Dd) + EPSf);
    #pragma unroll
    for (int w = 0; w < 4; w++) {
        int idx = w*128 + lane*4;
        float4 gg = *(const float4*)&g[idx];
        float4 bb = *(const float4*)&b[idx];
        float y0 = v[w].x*inv*gg.x + bb.x, y1 = v[w].y*inv*gg.y + bb.y;
        float y2 = v[w].z*inv*gg.z + bb.z, y3 = v[w].w*inv*gg.w + bb.w;
        if (of) {
            float4 o4 = {y0, y1, y2, y3};
            *(float4*)&of[(size_t)row*Dd + idx] = o4;
        } else {
            __nv_bfloat16 h0 = __float2bfloat16_rn(y0), h1 = __float2bfloat16_rn(y1);
            __nv_bfloat16 h2 = __float2bfloat16_rn(y2), h3 = __float2bfloat16_rn(y3);
            __nv_bfloat162 hp0(h0, h1), hp1(h2, h3);
            __nv_bfloat162 lp0(__float2bfloat16_rn(y0 - bf2f(h0)), __float2bfloat16_rn(y1 - bf2f(h1)));
            __nv_bfloat162 lp1(__float2bfloat16_rn(y2 - bf2f(h2)), __float2bfloat16_rn(y3 - bf2f(h3)));
            uint2 uh = { *(uint32_t*)&hp0, *(uint32_t*)&hp1 };
            uint2 ul = { *(uint32_t*)&lp0, *(uint32_t*)&lp1 };
            *(uint2*)&ohi[(size_t)row*Dd + idx] = uh;
            *(uint2*)&olo[(size_t)row*Dd + idx] = ul;
        }
    }
}

// ---------------- fused attention: all-MMA scores + PV -------------------------
#define SCS 520
#define ASMEM_TOTAL 110080
__global__ __launch_bounds__(256, 2) void attn_kernel(const float* __restrict__ relk,
                                                      const float* __restrict__ relv) {
    extern __shared__ char smx[];
    __nv_bfloat16* khi = (__nv_bfloat16*)smx;
    __nv_bfloat16* klo = (__nv_bfloat16*)(smx + 18432);
    float* sc   = (float*)(smx + 36864);
    __nv_bfloat16* phh = (__nv_bfloat16*)(smx + 70144);
    __nv_bfloat16* pll = (__nv_bfloat16*)(smx + 86784);
    __nv_bfloat16* qhi = (__nv_bfloat16*)(smx + 103424);
    __nv_bfloat16* qlo = (__nv_bfloat16*)(smx + 105728);
    float* qrs  = (float*)(smx + 108032);
    float* pbin = (float*)(smx + 109056);

    const int tid = threadIdx.x, w = tid >> 5, lane = tid & 31;
    const int n0 = blockIdx.x*16, h = blockIdx.y, b = blockIdx.z;
    const size_t tokbase = (size_t)(b*Nn);

    {
        int tensor = tid >> 7, idx = tid & 127, r = idx >> 3, cg = idx & 7;
        const __nv_bfloat16* src = (tensor ? g_qkvlo : g_qkvhi)
            + (tokbase + n0 + r)*1536 + h*DHd + cg*8;
        __nv_bfloat16* dst = (tensor ? qlo : qhi) + r*72 + cg*8;
        *(uint4*)dst = *(const uint4*)src;
    }
    pbin[tid] = 0.f;
    for (int i = tid; i < 2048; i += 256) {
        int tensor = i >> 10, idx = i & 1023, r = idx >> 3, cg = idx & 7;
        const __nv_bfloat16* src = (tensor ? g_qkvlo : g_qkvhi)
            + (tokbase + r)*1536 + Dd + h*DHd + cg*8;
        __nv_bfloat16* dst = (tensor ? klo : khi) + r*72 + cg*8;
        cpa16(dst, src);
    }
    CP_COMMIT();
    __syncthreads();

    if (tid < 16*Kb) {
        int qi = tid / Kb, j = tid % Kb;
        float dot = 0.f;
        #pragma unroll
        for (int d = 0; d < DHd; d++)
            dot += (bf2f(qhi[qi*72 + d]) + bf2f(qlo[qi*72 + d])) * relk[j*64 + d];
        qrs[qi*16 + j] = dot;
    }

    const int which = lane >> 3, rowin = lane & 7;
    const uint32_t aoff = (((which & 1)*8 + rowin)*72 + (which >> 1)*8)*2;
    const uint32_t boff = ((w*16 + (which >> 1)*8 + rowin)*72 + (which & 1)*8)*2;
    const uint32_t uQhi = smem_to_u32(qhi), uQlo = smem_to_u32(qlo);
    const uint32_t uKhi = smem_to_u32(khi), uKlo = smem_to_u32(klo);
    const int g = lane >> 2, t2 = (lane & 3)*2;

    for (int mc = 0; mc < 4; mc++) {
        if (mc == 0) {
            CP_WAIT(0);
        } else {
            for (int i = tid; i < 2048; i += 256) {
                int tensor = i >> 10, idx = i & 1023, r = idx >> 3, cg = idx & 7;
                const __nv_bfloat16* src = (tensor ? g_qkvlo : g_qkvhi)
                    + (tokbase + mc*128 + r)*1536 + Dd + h*DHd + cg*8;
                __nv_bfloat16* dst = (tensor ? klo : khi) + r*72 + cg*8;
                *(uint4*)dst = *(const uint4*)src;
            }
        }
        __syncthreads();
        float acc[2][4] = {};
        #pragma unroll
        for (int ks = 0; ks < 4; ks++) {
            uint32_t qh4[4], ql4[4], kh4[4], kl4[4];
            ldm_x4(qh4, uQhi + aoff + ks*32);
            ldm_x4(ql4, uQlo + aoff + ks*32);
            ldm_x4(kh4, uKhi + boff + ks*32);
            ldm_x4(kl4, uKlo + boff + ks*32);
            // term-major issue: max dependency distance between same-acc MMAs
            #pragma unroll
            for (int j = 0; j < 2; j++) mma16816(acc[j], qh4, &kh4[j*2]);
            #pragma unroll
            for (int j = 0; j < 2; j++) mma16816(acc[j], qh4, &kl4[j*2]);
            #pragma unroll
            for (int j = 0; j < 2; j++) mma16816(acc[j], ql4, &kh4[j*2]);
        }
        #pragma unroll
        for (int j = 0; j < 2; j++) {
            int m = mc*128 + w*16 + j*8 + t2;
            const unsigned char* ir0 = g_idx + (tokbase + n0 + g)*Nn + m;
            const unsigned char* ir1 = g_idx + (tokbase + n0 + g + 8)*Nn + m;
            sc[g*SCS + m]       = (acc[j][0] + qrs[g*16 + ir0[0]]) * 0.125f;
            sc[g*SCS + m + 1]   = (acc[j][1] + qrs[g*16 + ir0[1]]) * 0.125f;
            sc[(g+8)*SCS + m]   = (acc[j][2] + qrs[(g+8)*16 + ir1[0]]) * 0.125f;
            sc[(g+8)*SCS + m+1] = (acc[j][3] + qrs[(g+8)*16 + ir1[1]]) * 0.125f;
        }
        __syncthreads();
    }

    for (int i = tid; i < 2048; i += 256) {
        int tensor = i >> 10, idx = i & 1023, r = idx >> 3, cg = idx & 7;
        const __nv_bfloat16* src = (tensor ? g_qkvlo : g_qkvhi)
            + (tokbase + r)*1536 + 2*Dd + h*DHd + cg*8;
        __nv_bfloat16* dst = (tensor ? klo : khi) + r*72 + cg*8;
        cpa16(dst, src);
    }
    CP_COMMIT();

    #pragma unroll
    for (int rr = 0; rr < 2; rr++) {
        int row = w*2 + rr;
        float mx = -1e30f;
        for (int m = lane; m < 512; m += 32) mx = fmaxf(mx, sc[row*SCS + m]);
        #pragma unroll
        for (int o = 16; o > 0; o >>= 1) mx = fmaxf(mx, __shfl_xor_sync(~0u, mx, o));
        float sum = 0.f;
        for (int m = lane; m < 512; m += 32) {
            float e = fexp(sc[row*SCS + m] - mx);
            sc[row*SCS + m] = e; sum += e;
        }
        #pragma unroll
        for (int o = 16; o > 0; o >>= 1) sum += __shfl_xor_sync(~0u, sum, o);
        float inv = 1.f / sum;
        float pb[Kb];
        #pragma unroll
        for (int j = 0; j < Kb; j++) pb[j] = 0.f;
        const unsigned char* ir = g_idx + (tokbase + n0 + row)*Nn;
        for (int m = lane; m < 512; m += 32) {
            float p = sc[row*SCS + m] * inv;
            __nv_bfloat16 ph = __float2bfloat16_rn(p);
            phh[row*SCS + m] = ph;
            pll[row*SCS + m] = __float2bfloat16_rn(p - bf2f(ph));
            int ji = ir[m];
            #pragma unroll
            for (int j = 0; j < Kb; j++) if (ji == j) pb[j] += p;
        }
        #pragma unroll
        for (int j = 0; j < Kb; j++) {
            float v = pb[j];
            #pragma unroll
            for (int o = 16; o > 0; o >>= 1) v += __shfl_xor_sync(~0u, v, o);
            if (lane == 0) pbin[row*16 + j] = v;
        }
    }

    const int n0w = (w & 3)*16, khalf = w >> 2;
    const uint32_t uPh = smem_to_u32(phh), uPl = smem_to_u32(pll);
    const uint32_t paoff = (((which & 1)*8 + rowin)*SCS + (which >> 1)*8)*2;
    const uint32_t pboff = (((which & 1)*8 + rowin)*72 + n0w + (which >> 1)*8)*2;
    float c0[4] = {}, c1[4] = {};
    for (int mc = 0; mc < 4; mc++) {
        if (mc == 0) {
            CP_WAIT(0);
        } else {
            for (int i = tid; i < 2048; i += 256) {
                int tensor = i >> 10, idx = i & 1023, r = idx >> 3, cg = idx & 7;
                const __nv_bfloat16* src = (tensor ? g_qkvlo : g_qkvhi)
                    + (tokbase + mc*128 + r)*1536 + 2*Dd + h*DHd + cg*8;
                __nv_bfloat16* dst = (tensor ? klo : khi) + r*72 + cg*8;
                *(uint4*)dst = *(const uint4*)src;
            }
        }
        __syncthreads();
        #pragma unroll
        for (int ks = 0; ks < 4; ks++) {
            int kP = mc*128 + khalf*64 + ks*16;
            int kV = khalf*64 + ks*16;
            uint32_t ph4[4], pl4[4], vh4[4], vl4[4];
            ldm_x4(ph4, uPh + paoff + kP*2);
            ldm_x4(pl4, uPl + paoff + kP*2);
            ldm_x4t(vh4, uKhi + pboff + kV*144);
            ldm_x4t(vl4, uKlo + pboff + kV*144);
            // term-major issue
            mma16816(c0, ph4, &vh4[0]);
            mma16816(c1, ph4, &vh4[2]);
            mma16816(c0, ph4, &vl4[0]);
            mma16816(c1, ph4, &vl4[2]);
            mma16816(c0, pl4, &vh4[0]);
            mma16816(c1, pl4, &vh4[2]);
        }
        __syncthreads();
    }
    {
        float* outp = sc + khalf*(16*68);
        outp[g*68 + n0w + t2]          = c0[0];
        outp[g*68 + n0w + t2 + 1]      = c0[1];
        outp[(g+8)*68 + n0w + t2]      = c0[2];
        outp[(g+8)*68 + n0w + t2 + 1]  = c0[3];
        outp[g*68 + n0w + 8 + t2]      = c1[0];
        outp[g*68 + n0w + 8 + t2 + 1]  = c1[1];
        outp[(g+8)*68 + n0w + 8 + t2]  = c1[2];
        outp[(g+8)*68 + n0w + 8 + t2+1]= c1[3];
    }
    __syncthreads();
    for (int i = tid; i < 1024; i += 256) {
        int qi = i >> 6, d = i & 63;
        float o = sc[qi*68 + d] + sc[16*68 + qi*68 + d];
        #pragma unroll
        for (int j = 0; j < Kb; j++) o += pbin[qi*16 + j] * relv[j*64 + d];
        size_t tok = tokbase + n0 + qi;
        __nv_bfloat16 hb = __float2bfloat16_rn(o);
        g_ohi[tok*Dd + h*DHd + d] = hb;
        g_olo[tok*Dd + h*DHd + d] = __float2bfloat16_rn(o - bf2f(hb));
    }
}

// ---------------- bf16x3 mma GEMM, 3-stage cp.async + ldmatrix ----------------
// CTA 64(M)x128(N), BK=32, 256 thr, 8 warps 2x4 (warp 32x32). Term-major MMA issue.
#define SSTR 40
#define GSMEM_TOTAL 92160
__global__ __launch_bounds__(256, 2) void gemm_mma_kernel(
    const __nv_bfloat16* __restrict__ Ahi, const __nv_bfloat16* __restrict__ Alo,
    const __nv_bfloat16* __restrict__ Bhi, const __nv_bfloat16* __restrict__ Blo,
    const float* __restrict__ bias, const float* __restrict__ res,
    float* __restrict__ Cf, __nv_bfloat16* __restrict__ Chi, __nv_bfloat16* __restrict__ Clo,
    int Nc, int Kc, int doGelu) {
    extern __shared__ char smx[];
    __nv_bfloat16* sAhi = (__nv_bfloat16*)smx;
    __nv_bfloat16* sAlo = sAhi + 3*64*SSTR;
    __nv_bfloat16* sBhi = sAlo + 3*64*SSTR;
    __nv_bfloat16* sBlo = sBhi + 3*128*SSTR;

    const int tid = threadIdx.x, wid = tid >> 5, lane = tid & 31;
    const int g = lane >> 2, t2 = (lane & 3)*2;
    const int wm = (wid >> 2)*32, wn = (wid & 3)*32;
    const int m0 = blockIdx.y*64, n0 = blockIdx.x*128;

    const int ar = tid >> 2, ac = (tid & 3)*8;
    const int br0 = tid >> 2, bc0 = (tid & 3)*8;
    const int br1 = (tid + 256) >> 2, bc1 = ((tid + 256) & 3)*8;

    const int which = lane >> 3, rowin = lane & 7;
    uint32_t aoff[2], boff[2];
    #pragma unroll
    for (int i = 0; i < 2; i++)
        aoff[i] = ((wm + i*16 + (which & 1)*8 + rowin)*SSTR + (which >> 1)*8)*2;
    #pragma unroll
    for (int p = 0; p < 2; p++)
        boff[p] = ((wn + p*16 + (which >> 1)*8 + rowin)*SSTR + (which & 1)*8)*2;
    const uint32_t uAhi = smem_to_u32(sAhi), uAlo = smem_to_u32(sAlo);
    const uint32_t uBhi = smem_to_u32(sBhi), uBlo = smem_to_u32(sBlo);

    auto issue = [&](int c, int buf) {
        int kc = c*32;
        cpa16(&sAhi[buf*(64*SSTR) + ar*SSTR + ac], Ahi + (size_t)(m0 + ar)*Kc + kc + ac);
        cpa16(&sAlo[buf*(64*SSTR) + ar*SSTR + ac], Alo + (size_t)(m0 + ar)*Kc + kc + ac);
        cpa16(&sBhi[buf*(128*SSTR) + br0*SSTR + bc0], Bhi + (size_t)(n0 + br0)*Kc + kc + bc0);
        cpa16(&sBhi[buf*(128*SSTR) + br1*SSTR + bc1], Bhi + (size_t)(n0 + br1)*Kc + kc + bc1);
        cpa16(&sBlo[buf*(128*SSTR) + br0*SSTR + bc0], Blo + (size_t)(n0 + br0)*Kc + kc + bc0);
        cpa16(&sBlo[buf*(128*SSTR) + br1*SSTR + bc1], Blo + (size_t)(n0 + br1)*Kc + kc + bc1);
    };

    float acc[2][4][4] = {};
    const int nch = Kc >> 5;
    issue(0, 0); CP_COMMIT();
    issue(1, 1); CP_COMMIT();

    for (int c = 0; c < nch; c++) {
        int buf = c % 3;
        if (c + 2 < nch) {
            CP_WAIT(1);
            __syncthreads();
            issue(c + 2, (c + 2) % 3);
            CP_COMMIT();
        } else {
            CP_WAIT(0);
            __syncthreads();
        }
        const uint32_t offA = buf*(64*SSTR*2), offB = buf*(128*SSTR*2);
        #pragma unroll
        for (int ks = 0; ks < 32; ks += 16) {
            uint32_t ah[2][4], al[2][4], bh[8], bl[8];
            #pragma unroll
            for (int i = 0; i < 2; i++) {
                ldm_x4(ah[i], uAhi + offA + aoff[i] + ks*2);
                ldm_x4(al[i], uAlo + offA + aoff[i] + ks*2);
            }
            #pragma unroll
            for (int p = 0; p < 2; p++) {
                ldm_x4(&bh[p*4], uBhi + offB + boff[p] + ks*2);
                ldm_x4(&bl[p*4], uBlo + offB + boff[p] + ks*2);
            }
            // term-major: 8 independent accumulators between same-acc MMAs
            #pragma unroll
            for (int i = 0; i < 2; i++)
                #pragma unroll
                for (int j = 0; j < 4; j++) mma16816(acc[i][j], ah[i], &bh[j*2]);
            #pragma unroll
            for (int i = 0; i < 2; i++)
                #pragma unroll
                for (int j = 0; j < 4; j++) mma16816(acc[i][j], ah[i], &bl[j*2]);
            #pragma unroll
            for (int i = 0; i < 2; i++)
                #pragma unroll
                for (int j = 0; j < 4; j++) mma16816(acc[i][j], al[i], &bh[j*2]);
        }
    }

    #pragma unroll
    for (int i = 0; i < 2; i++) {
        int r0 = m0 + wm + i*16 + g;
        #pragma unroll
        for (int j = 0; j < 4; j++) {
            int col = n0 + wn + j*8 + t2;
            float b0 = bias[col], b1 = bias[col + 1];
            float2 v0 = { acc[i][j][0] + b0, acc[i][j][1] + b1 };
            float2 v1 = { acc[i][j][2] + b0, acc[i][j][3] + b1 };
            if (res) {
                float2 r0v = *(const float2*)&res[(size_t)r0*Nc + col];
                float2 r1v = *(const float2*)&res[(size_t)(r0 + 8)*Nc + col];
                v0.x += r0v.x; v0.y += r0v.y; v1.x += r1v.x; v1.y += r1v.y;
            }
            if (doGelu) {
                v0.x = 0.5f*v0.x*(1.f + erff(v0.x*0.70710678118654752f));
                v0.y = 0.5f*v0.y*(1.f + erff(v0.y*0.70710678118654752f));
                v1.x = 0.5f*v1.x*(1.f + erff(v1.x*0.70710678118654752f));
                v1.y = 0.5f*v1.y*(1.f + erff(v1.y*0.70710678118654752f));
            }
            if (Chi) {
                __nv_bfloat16 h00 = __float2bfloat16_rn(v0.x), h01 = __float2bfloat16_rn(v0.y);
                __nv_bfloat16 h10 = __float2bfloat16_rn(v1.x), h11 = __float2bfloat16_rn(v1.y);
                __nv_bfloat162 hp0(h00, h01), hp1(h10, h11);
                __nv_bfloat162 lp0(__float2bfloat16_rn(v0.x - bf2f(h00)), __float2bfloat16_rn(v0.y - bf2f(h01)));
                __nv_bfloat162 lp1(__float2bfloat16_rn(v1.x - bf2f(h10)), __float2bfloat16_rn(v1.y - bf2f(h11)));
                *(uint32_t*)&Chi[(size_t)r0*Nc + col]       = *(uint32_t*)&hp0;
                *(uint32_t*)&Chi[(size_t)(r0 + 8)*Nc + col] = *(uint32_t*)&hp1;
                *(uint32_t*)&Clo[(size_t)r0*Nc + col]       = *(uint32_t*)&lp0;
                *(uint32_t*)&Clo[(size_t)(r0 + 8)*Nc + col] = *(uint32_t*)&lp1;
            }
            if (Cf) {
                *(float2*)&Cf[(size_t)r0*Nc + col]       = v0;
                *(float2*)&Cf[(size_t)(r0 + 8)*Nc + col] = v1;
            }
        }
    }
}

// ---------------------------------------------------------------------------
extern "C" void kernel_launch(void* const* d_in, const int* in_sizes, int n_in,
                              void* d_out, int out_size) {
    const float* x     = (const float*)d_in[0];
    const float* coord = (const float*)d_in[1];
    const float* ln1_g = (const float*)d_in[2];
    const float* ln1_b = (const float*)d_in[3];
    const float* wq    = (const float*)d_in[4];
    const float* bq    = (const float*)d_in[5];
    const float* wk    = (const float*)d_in[6];
    const float* bk    = (const float*)d_in[7];
    const float* wv    = (const float*)d_in[8];
    const float* bv    = (const float*)d_in[9];
    const float* wo    = (const float*)d_in[10];
    const float* bo    = (const float*)d_in[11];
    const float* rel_k = (const float*)d_in[12];
    const float* rel_v = (const float*)d_in[13];
    const float* ln2_g = (const float*)d_in[14];
    const float* ln2_b = (const float*)d_in[15];
    const float* w1    = (const float*)d_in[16];
    const float* b1    = (const float*)d_in[17];
    const float* w2    = (const float*)d_in[18];
    const float* b2    = (const float*)d_in[19];
    const float* lnf_g = (const float*)d_in[20];
    const float* lnf_b = (const float*)d_in[21];

    float *px, *pbqkv;
    __nv_bfloat16 *pqkvhi, *pqkvlo, *phhi, *phlo, *pohi, *polo, *pfhi, *pflo, *pwhi, *pwlo;
    cudaGetSymbolAddress((void**)&px,     g_x);
    cudaGetSymbolAddress((void**)&pbqkv,  g_bqkv);
    cudaGetSymbolAddress((void**)&pqkvhi, g_qkvhi);
    cudaGetSymbolAddress((void**)&pqkvlo, g_qkvlo);
    cudaGetSymbolAddress((void**)&phhi,   g_hhi);
    cudaGetSymbolAddress((void**)&phlo,   g_hlo);
    cudaGetSymbolAddress((void**)&pohi,   g_ohi);
    cudaGetSymbolAddress((void**)&polo,   g_olo);
    cudaGetSymbolAddress((void**)&pfhi,   g_fhi);
    cudaGetSymbolAddress((void**)&pflo,   g_flo);
    cudaGetSymbolAddress((void**)&pwhi,   g_whi);
    cudaGetSymbolAddress((void**)&pwlo,   g_wlo);

    cudaFuncSetAttribute(gemm_mma_kernel, cudaFuncAttributeMaxDynamicSharedMemorySize, GSMEM_TOTAL);
    cudaFuncSetAttribute(attn_kernel, cudaFuncAttributeMaxDynamicSharedMemorySize, ASMEM_TOTAL);

    // Order keeps ncu capture window on the layer-0 QKV GEMM.
    cudaMemcpyAsync(px, x, sizeof(float)*TOK*Dd, cudaMemcpyDeviceToDevice);
    biaspack_kernel<<<(Ll*1536 + 255)/256, 256>>>(bq, bk, bv);
    wconv_all_kernel<<<dim3(16, 16, Ll*6), dim3(32, 8)>>>(wq, wk, wv, wo, w1, w2);

    const dim3 gQKV(12, 32);   // N=1536
    const dim3 gPRJ(4, 32);    // N=512
    const dim3 gFF1(16, 32);   // N=2048

    for (int l = 0; l < Ll; l++) {
        size_t lo = (size_t)l * WL_STRIDE;
        ln_kernel<<<TOK/8, 256>>>(px, ln1_g + l*Dd, ln1_b + l*Dd, phhi, phlo, nullptr);
        gemm_mma_kernel<<<gQKV, 256, GSMEM_TOTAL>>>(
            phhi, phlo, pwhi + lo, pwlo + lo, pbqkv + l*1536, nullptr,
            nullptr, pqkvhi, pqkvlo, 1536, 512, 0);
        if (l == 0) idx_kernel<<<dim3(Nn, Bb), Nn>>>(coord);
        attn_kernel<<<dim3(Nn/16, Hh, Bb), 256, ASMEM_TOTAL>>>(
            rel_k + (size_t)l*Kb*DHd, rel_v + (size_t)l*Kb*DHd);
        gemm_mma_kernel<<<gPRJ, 256, GSMEM_TOTAL>>>(
            pohi, polo, pwhi + lo + 786432, pwlo + lo + 786432, bo + l*Dd, px,
            px, nullptr, nullptr, 512, 512, 0);
        ln_kernel<<<TOK/8, 256>>>(px, ln2_g + l*Dd, ln2_b + l*Dd, phhi, phlo, nullptr);
        gemm_mma_kernel<<<gFF1, 256, GSMEM_TOTAL>>>(
            phhi, phlo, pwhi + lo + 1048576, pwlo + lo + 1048576, b1 + l*Mf, nullptr,
            nullptr, pfhi, pflo, 2048, 512, 1);
        gemm_mma_kernel<<<gPRJ, 256, GSMEM_TOTAL>>>(
            pfhi, pflo, pwhi + lo + 2097152, pwlo + lo + 2097152, b2 + l*Dd, px,
            px, nullptr, nullptr, 512, 2048, 0);
    }
    ln_kernel<<<TOK/8, 256>>>(px, lnf_g, lnf_b, nullptr, nullptr, (float*)d_out);
}

// round 15
// speedup vs baseline: 1.0725x; 1.0419x over previous
#include <cuda_runtime.h>
#include <cuda_bf16.h>
#include <cstdint>
#include <math.h>

// Problem constants
#define Bb   4
#define Nn   512
#define Dd   512
#define Hh   8
#define DHd  64
#define Kb   10
#define Mf   2048
#define Ll   4
#define TOK  (Bb*Nn)      // 2048
#define EPSf 1e-5f

// ---------------- scratch (device globals) ----------------------------------
__device__ float g_x[TOK*Dd];
__device__ unsigned char g_idx[Bb*Nn*Nn];
__device__ __nv_bfloat16 g_qkvhi[TOK*1536], g_qkvlo[TOK*1536];
__device__ __nv_bfloat16 g_hhi[TOK*Dd], g_hlo[TOK*Dd];
__device__ __nv_bfloat16 g_ohi[TOK*Dd], g_olo[TOK*Dd];
__device__ __nv_bfloat16 g_fhi[TOK*Mf], g_flo[TOK*Mf];
#define WL_STRIDE 3145728
__device__ __nv_bfloat16 g_whi[Ll*WL_STRIDE], g_wlo[Ll*WL_STRIDE];
__device__ float g_bqkv[Ll*1536];

// ---------------- helpers ----------------------------------------------------
__device__ __forceinline__ uint32_t smem_to_u32(const void* p) {
    uint32_t a;
    asm("{ .reg .u64 t; cvta.to.shared.u64 t, %1; cvt.u32.u64 %0, t; }"
        : "=r"(a) : "l"(p));
    return a;
}
__device__ __forceinline__ void cpa16(void* dst, const void* src) {
    uint32_t d = smem_to_u32(dst);
    asm volatile("cp.async.cg.shared.global [%0], [%1], 16;" :: "r"(d), "l"(src));
}
#define CP_COMMIT() asm volatile("cp.async.commit_group;" ::: "memory")
#define CP_WAIT(n)  asm volatile("cp.async.wait_group %0;" :: "n"(n) : "memory")

__device__ __forceinline__ void mma16816(float* c, const uint32_t* a, const uint32_t* b) {
    asm volatile("mma.sync.aligned.m16n8k16.row.col.f32.bf16.bf16.f32 "
        "{%0,%1,%2,%3}, {%4,%5,%6,%7}, {%8,%9}, {%0,%1,%2,%3};"
        : "+f"(c[0]), "+f"(c[1]), "+f"(c[2]), "+f"(c[3])
        : "r"(a[0]), "r"(a[1]), "r"(a[2]), "r"(a[3]), "r"(b[0]), "r"(b[1]));
}
__device__ __forceinline__ void ldm_x4(uint32_t* r, uint32_t addr) {
    asm volatile("ldmatrix.sync.aligned.m8n8.x4.shared.b16 {%0,%1,%2,%3}, [%4];"
        : "=r"(r[0]), "=r"(r[1]), "=r"(r[2]), "=r"(r[3]) : "r"(addr));
}
__device__ __forceinline__ void ldm_x4t(uint32_t* r, uint32_t addr) {
    asm volatile("ldmatrix.sync.aligned.m8n8.x4.trans.shared.b16 {%0,%1,%2,%3}, [%4];"
        : "=r"(r[0]), "=r"(r[1]), "=r"(r[2]), "=r"(r[3]) : "r"(addr));
}
__device__ __forceinline__ float bf2f(__nv_bfloat16 h) { return __bfloat162float(h); }

// FMA-pipe exp (rel err ~2e-6, x<=0)
__device__ __forceinline__ float fexp(float x) {
    float t = x * 1.4426950408889634f;
    float n = rintf(t);
    float f = t - n;
    float p = 1.3534581e-3f;
    p = fmaf(p, f, 9.6181291e-3f);
    p = fmaf(p, f, 5.5504109e-2f);
    p = fmaf(p, f, 2.4022651e-1f);
    p = fmaf(p, f, 6.9314718e-1f);
    p = fmaf(p, f, 1.0f);
    return p * __int_as_float(((int)n + 127) << 23);
}

// ---------------- setup: weights + bias pack + idx in ONE launch --------------
// grid (16,16,Ll*6+2), block (32,8)=256. z<Ll*6: weight transpose+split;
// z==Ll*6: bias pack; z==Ll*6+1: distance bins.
__global__ void setup_all_kernel(const float* __restrict__ wq, const float* __restrict__ wk,
                                 const float* __restrict__ wv, const float* __restrict__ wo,
                                 const float* __restrict__ w1, const float* __restrict__ w2,
                                 const float* __restrict__ bq, const float* __restrict__ bk,
                                 const float* __restrict__ bv, const float* __restrict__ coord) {
    __shared__ float t[32][33];
    int z = blockIdx.z;
    int tx = threadIdx.x, ty = threadIdx.y;
    int tid = ty*32 + tx;
    int bb = blockIdx.y*16 + blockIdx.x;    // 0..255

    if (z == Ll*6) {        // bias pack: Ll*1536 = 6144 elems
        int i = bb*256 + tid;
        if (i < Ll*1536) {
            int l = i / 1536, c = i % 1536;
            g_bqkv[i] = (c < 512) ? bq[l*512 + c]
                      : (c < 1024 ? bk[l*512 + c - 512] : bv[l*512 + c - 1024]);
        }
        return;
    }
    if (z == Ll*6 + 1) {    // idx: 2048 rows x 512
        #pragma unroll
        for (int r = 0; r < 8; r++) {
            int row = bb*8 + r;            // 0..2047
            int n = row & (Nn-1), b = row >> 9;
            float2 cn = ((const float2*)coord)[b*Nn + n];
            #pragma unroll
            for (int half = 0; half < 2; half++) {
                int m = tid + half*256;
                float2 cm = ((const float2*)coord)[b*Nn + m];
                float dx = cn.x - cm.x, dy = cn.y - cm.y;
                float dist = sqrtf(dx*dx + dy*dy);
                int j = (int)floorf(dist);
                j = j < 0 ? 0 : (j > Kb-1 ? Kb-1 : j);
                g_idx[((size_t)(b*Nn + n))*Nn + m] = (unsigned char)j;
            }
        }
        return;
    }

    int l = z / 6, job = z % 6;
    const float* W; int K, N; size_t off;
    switch (job) {
        case 0: W = wq + (size_t)l*Dd*Dd; K = 512;  N = 512;  off = 0;       break;
        case 1: W = wk + (size_t)l*Dd*Dd; K = 512;  N = 512;  off = 262144;  break;
        case 2: W = wv + (size_t)l*Dd*Dd; K = 512;  N = 512;  off = 524288;  break;
        case 3: W = wo + (size_t)l*Dd*Dd; K = 512;  N = 512;  off = 786432;  break;
        case 4: W = w1 + (size_t)l*Dd*Mf; K = 512;  N = 2048; off = 1048576; break;
        default:W = w2 + (size_t)l*Mf*Dd; K = 2048; N = 512;  off = 2097152; break;
    }
    __nv_bfloat16* dh = g_whi + (size_t)l*WL_STRIDE + off;
    __nv_bfloat16* dl = g_wlo + (size_t)l*WL_STRIDE + off;
    int reps = (job >= 4) ? 4 : 1;
    for (int r = 0; r < reps; r++) {
        int nn0, k0;
        if (job == 4)      { nn0 = (blockIdx.x + 16*r)*32; k0 = blockIdx.y*32; }
        else if (job == 5) { nn0 = blockIdx.x*32; k0 = (blockIdx.y + 16*r)*32; }
        else               { nn0 = blockIdx.x*32; k0 = blockIdx.y*32; }
        #pragma unroll
        for (int i = 0; i < 4; i++)
            t[ty + i*8][tx] = W[(size_t)(k0 + ty + i*8)*N + nn0 + tx];
        __syncthreads();
        #pragma unroll
        for (int i = 0; i < 4; i++) {
            int nl = ty + i*8;
            float v = t[tx][nl];
            __nv_bfloat16 hb = __float2bfloat16_rn(v);
            size_t o = (size_t)(nn0 + nl)*K + k0 + tx;
            dh[o] = hb; dl[o] = __float2bfloat16_rn(v - bf2f(hb));
        }
        __syncthreads();
    }
}

// ---------------- layernorm: warp per row, 8 rows/block ------------------------
__global__ __launch_bounds__(256) void ln_kernel(
    const float* __restrict__ x, const float* __restrict__ g, const float* __restrict__ b,
    __nv_bfloat16* __restrict__ ohi, __nv_bfloat16* __restrict__ olo,
    float* __restrict__ of) {
    int wid = threadIdx.x >> 5, lane = threadIdx.x & 31;
    int row = blockIdx.x*8 + wid;
    const float* xr = x + (size_t)row*Dd;
    float4 v[4];
    float sum = 0.f;
    #pragma unroll
    for (int w = 0; w < 4; w++) {
        v[w] = *(const float4*)&xr[w*128 + lane*4];
        sum += v[w].x + v[w].y + v[w].z + v[w].w;
    }
    #pragma unroll
    for (int o = 16; o > 0; o >>= 1) sum += __shfl_xor_sync(~0u, sum, o);
    float mean = sum * (1.0f / Dd);
    float var = 0.f;
    #pragma unroll
    for (int w = 0; w < 4; w++) {
        v[w].x -= mean; v[w].y -= mean; v[w].z -= mean; v[w].w -= mean;
        var += v[w].x*v[w].x + v[w].y*v[w].y + v[w].z*v[w].z + v[w].w*v[w].w;
    }
    #pragma unroll
    for (int o = 16; o > 0; o >>= 1) var += __shfl_xor_sync(~0u, var, o);
    float inv = rsqrtf(var * (1.0f / Dd) + EPSf);
    #pragma unroll
    for (int w = 0; w < 4; w++) {
        int idx = w*128 + lane*4;
        float4 gg = *(const float4*)&g[idx];
        float4 bb = *(const float4*)&b[idx];
        float y0 = v[w].x*inv*gg.x + bb.x, y1 = v[w].y*inv*gg.y + bb.y;
        float y2 = v[w].z*inv*gg.z + bb.z, y3 = v[w].w*inv*gg.w + bb.w;
        if (of) {
            float4 o4 = {y0, y1, y2, y3};
            *(float4*)&of[(size_t)row*Dd + idx] = o4;
        } else {
            __nv_bfloat16 h0 = __float2bfloat16_rn(y0), h1 = __float2bfloat16_rn(y1);
            __nv_bfloat16 h2 = __float2bfloat16_rn(y2), h3 = __float2bfloat16_rn(y3);
            __nv_bfloat162 hp0(h0, h1), hp1(h2, h3);
            __nv_bfloat162 lp0(__float2bfloat16_rn(y0 - bf2f(h0)), __float2bfloat16_rn(y1 - bf2f(h1)));
            __nv_bfloat162 lp1(__float2bfloat16_rn(y2 - bf2f(h2)), __float2bfloat16_rn(y3 - bf2f(h3)));
            uint2 uh = { *(uint32_t*)&hp0, *(uint32_t*)&hp1 };
            uint2 ul = { *(uint32_t*)&lp0, *(uint32_t*)&lp1 };
            *(uint2*)&ohi[(size_t)row*Dd + idx] = uh;
            *(uint2*)&olo[(size_t)row*Dd + idx] = ul;
        }
    }
}

// ---------------- fused attention: all-MMA scores + PV -------------------------
#define SCS 520
#define ASMEM_TOTAL 110080
__global__ __launch_bounds__(256, 2) void attn_kernel(const float* __restrict__ relk,
                                                      const float* __restrict__ relv) {
    extern __shared__ char smx[];
    __nv_bfloat16* khi = (__nv_bfloat16*)smx;
    __nv_bfloat16* klo = (__nv_bfloat16*)(smx + 18432);
    float* sc   = (float*)(smx + 36864);
    __nv_bfloat16* phh = (__nv_bfloat16*)(smx + 70144);
    __nv_bfloat16* pll = (__nv_bfloat16*)(smx + 86784);
    __nv_bfloat16* qhi = (__nv_bfloat16*)(smx + 103424);
    __nv_bfloat16* qlo = (__nv_bfloat16*)(smx + 105728);
    float* qrs  = (float*)(smx + 108032);
    float* pbin = (float*)(smx + 109056);

    const int tid = threadIdx.x, w = tid >> 5, lane = tid & 31;
    const int n0 = blockIdx.x*16, h = blockIdx.y, b = blockIdx.z;
    const size_t tokbase = (size_t)(b*Nn);

    {
        int tensor = tid >> 7, idx = tid & 127, r = idx >> 3, cg = idx & 7;
        const __nv_bfloat16* src = (tensor ? g_qkvlo : g_qkvhi)
            + (tokbase + n0 + r)*1536 + h*DHd + cg*8;
        __nv_bfloat16* dst = (tensor ? qlo : qhi) + r*72 + cg*8;
        *(uint4*)dst = *(const uint4*)src;
    }
    pbin[tid] = 0.f;
    for (int i = tid; i < 2048; i += 256) {
        int tensor = i >> 10, idx = i & 1023, r = idx >> 3, cg = idx & 7;
        const __nv_bfloat16* src = (tensor ? g_qkvlo : g_qkvhi)
            + (tokbase + r)*1536 + Dd + h*DHd + cg*8;
        __nv_bfloat16* dst = (tensor ? klo : khi) + r*72 + cg*8;
        cpa16(dst, src);
    }
    CP_COMMIT();
    __syncthreads();

    if (tid < 16*Kb) {
        int qi = tid / Kb, j = tid % Kb;
        float dot = 0.f;
        #pragma unroll
        for (int d = 0; d < DHd; d++)
            dot += (bf2f(qhi[qi*72 + d]) + bf2f(qlo[qi*72 + d])) * relk[j*64 + d];
        qrs[qi*16 + j] = dot;
    }

    const int which = lane >> 3, rowin = lane & 7;
    const uint32_t aoff = (((which & 1)*8 + rowin)*72 + (which >> 1)*8)*2;
    const uint32_t boff = ((w*16 + (which >> 1)*8 + rowin)*72 + (which & 1)*8)*2;
    const uint32_t uQhi = smem_to_u32(qhi), uQlo = smem_to_u32(qlo);
    const uint32_t uKhi = smem_to_u32(khi), uKlo = smem_to_u32(klo);
    const int g = lane >> 2, t2 = (lane & 3)*2;

    for (int mc = 0; mc < 4; mc++) {
        if (mc > 0) {
            for (int i = tid; i < 2048; i += 256) {
                int tensor = i >> 10, idx = i & 1023, r = idx >> 3, cg = idx & 7;
                const __nv_bfloat16* src = (tensor ? g_qkvlo : g_qkvhi)
                    + (tokbase + mc*128 + r)*1536 + Dd + h*DHd + cg*8;
                __nv_bfloat16* dst = (tensor ? klo : khi) + r*72 + cg*8;
                cpa16(dst, src);
            }
            CP_COMMIT();
        }
        CP_WAIT(0);
        __syncthreads();
        float acc[2][4] = {};
        #pragma unroll
        for (int ks = 0; ks < 4; ks++) {
            uint32_t qh4[4], ql4[4], kh4[4], kl4[4];
            ldm_x4(qh4, uQhi + aoff + ks*32);
            ldm_x4(ql4, uQlo + aoff + ks*32);
            ldm_x4(kh4, uKhi + boff + ks*32);
            ldm_x4(kl4, uKlo + boff + ks*32);
            #pragma unroll
            for (int j = 0; j < 2; j++) {
                mma16816(acc[j], qh4, &kh4[j*2]);
                mma16816(acc[j], qh4, &kl4[j*2]);
                mma16816(acc[j], ql4, &kh4[j*2]);
            }
        }
        #pragma unroll
        for (int j = 0; j < 2; j++) {
            int m = mc*128 + w*16 + j*8 + t2;
            const unsigned char* ir0 = g_idx + (tokbase + n0 + g)*Nn + m;
            const unsigned char* ir1 = g_idx + (tokbase + n0 + g + 8)*Nn + m;
            sc[g*SCS + m]       = (acc[j][0] + qrs[g*16 + ir0[0]]) * 0.125f;
            sc[g*SCS + m + 1]   = (acc[j][1] + qrs[g*16 + ir0[1]]) * 0.125f;
            sc[(g+8)*SCS + m]   = (acc[j][2] + qrs[(g+8)*16 + ir1[0]]) * 0.125f;
            sc[(g+8)*SCS + m+1] = (acc[j][3] + qrs[(g+8)*16 + ir1[1]]) * 0.125f;
        }
        __syncthreads();
    }

    for (int i = tid; i < 2048; i += 256) {
        int tensor = i >> 10, idx = i & 1023, r = idx >> 3, cg = idx & 7;
        const __nv_bfloat16* src = (tensor ? g_qkvlo : g_qkvhi)
            + (tokbase + r)*1536 + 2*Dd + h*DHd + cg*8;
        __nv_bfloat16* dst = (tensor ? klo : khi) + r*72 + cg*8;
        cpa16(dst, src);
    }
    CP_COMMIT();

    #pragma unroll
    for (int rr = 0; rr < 2; rr++) {
        int row = w*2 + rr;
        float mx = -1e30f;
        for (int m = lane; m < 512; m += 32) mx = fmaxf(mx, sc[row*SCS + m]);
        #pragma unroll
        for (int o = 16; o > 0; o >>= 1) mx = fmaxf(mx, __shfl_xor_sync(~0u, mx, o));
        float sum = 0.f;
        for (int m = lane; m < 512; m += 32) {
            float e = fexp(sc[row*SCS + m] - mx);
            sc[row*SCS + m] = e; sum += e;
        }
        #pragma unroll
        for (int o = 16; o > 0; o >>= 1) sum += __shfl_xor_sync(~0u, sum, o);
        float inv = 1.f / sum;
        float pb[Kb];
        #pragma unroll
        for (int j = 0; j < Kb; j++) pb[j] = 0.f;
        const unsigned char* ir = g_idx + (tokbase + n0 + row)*Nn;
        for (int m = lane; m < 512; m += 32) {
            float p = sc[row*SCS + m] * inv;
            __nv_bfloat16 ph = __float2bfloat16_rn(p);
            phh[row*SCS + m] = ph;
            pll[row*SCS + m] = __float2bfloat16_rn(p - bf2f(ph));
            int ji = ir[m];
            #pragma unroll
            for (int j = 0; j < Kb; j++) if (ji == j) pb[j] += p;
        }
        #pragma unroll
        for (int j = 0; j < Kb; j++) {
            float v = pb[j];
            #pragma unroll
            for (int o = 16; o > 0; o >>= 1) v += __shfl_xor_sync(~0u, v, o);
            if (lane == 0) pbin[row*16 + j] = v;
        }
    }

    const int n0w = (w & 3)*16, khalf = w >> 2;
    const uint32_t uPh = smem_to_u32(phh), uPl = smem_to_u32(pll);
    const uint32_t paoff = (((which & 1)*8 + rowin)*SCS + (which >> 1)*8)*2;
    const uint32_t pboff = (((which & 1)*8 + rowin)*72 + n0w + (which >> 1)*8)*2;
    float c0[4] = {}, c1[4] = {};
    for (int mc = 0; mc < 4; mc++) {
        if (mc > 0) {
            for (int i = tid; i < 2048; i += 256) {
                int tensor = i >> 10, idx = i & 1023, r = idx >> 3, cg = idx & 7;
                const __nv_bfloat16* src = (tensor ? g_qkvlo : g_qkvhi)
                    + (tokbase + mc*128 + r)*1536 + 2*Dd + h*DHd + cg*8;
                __nv_bfloat16* dst = (tensor ? klo : khi) + r*72 + cg*8;
                cpa16(dst, src);
            }
            CP_COMMIT();
        }
        CP_WAIT(0);
        __syncthreads();
        #pragma unroll
        for (int ks = 0; ks < 4; ks++) {
            int kP = mc*128 + khalf*64 + ks*16;
            int kV = khalf*64 + ks*16;
            uint32_t ph4[4], pl4[4], vh4[4], vl4[4];
            ldm_x4(ph4, uPh + paoff + kP*2);
            ldm_x4(pl4, uPl + paoff + kP*2);
            ldm_x4t(vh4, uKhi + pboff + kV*144);
            ldm_x4t(vl4, uKlo + pboff + kV*144);
            mma16816(c0, ph4, &vh4[0]);
            mma16816(c0, ph4, &vl4[0]);
            mma16816(c0, pl4, &vh4[0]);
            mma16816(c1, ph4, &vh4[2]);
            mma16816(c1, ph4, &vl4[2]);
            mma16816(c1, pl4, &vh4[2]);
        }
        __syncthreads();
    }
    {
        float* outp = sc + khalf*(16*68);
        outp[g*68 + n0w + t2]          = c0[0];
        outp[g*68 + n0w + t2 + 1]      = c0[1];
        outp[(g+8)*68 + n0w + t2]      = c0[2];
        outp[(g+8)*68 + n0w + t2 + 1]  = c0[3];
        outp[g*68 + n0w + 8 + t2]      = c1[0];
        outp[g*68 + n0w + 8 + t2 + 1]  = c1[1];
        outp[(g+8)*68 + n0w + 8 + t2]  = c1[2];
        outp[(g+8)*68 + n0w + 8 + t2+1]= c1[3];
    }
    __syncthreads();
    for (int i = tid; i < 1024; i += 256) {
        int qi = i >> 6, d = i & 63;
        float o = sc[qi*68 + d] + sc[16*68 + qi*68 + d];
        #pragma unroll
        for (int j = 0; j < Kb; j++) o += pbin[qi*16 + j] * relv[j*64 + d];
        size_t tok = tokbase + n0 + qi;
        __nv_bfloat16 hb = __float2bfloat16_rn(o);
        g_ohi[tok*Dd + h*DHd + d] = hb;
        g_olo[tok*Dd + h*DHd + d] = __float2bfloat16_rn(o - bf2f(hb));
    }
}

// ---------------- bf16x3 mma GEMM, 3-stage cp.async + ldmatrix ----------------
// CTA 64(M)x128(N), BK=32, 256 thr, 8 warps 2x4 (warp 32x32).
#define SSTR 40
#define GSMEM_TOTAL 92160
__global__ __launch_bounds__(256, 2) void gemm_mma_kernel(
    const __nv_bfloat16* __restrict__ Ahi, const __nv_bfloat16* __restrict__ Alo,
    const __nv_bfloat16* __restrict__ Bhi, const __nv_bfloat16* __restrict__ Blo,
    const float* __restrict__ bias, const float* __restrict__ res,
    float* __restrict__ Cf, __nv_bfloat16* __restrict__ Chi, __nv_bfloat16* __restrict__ Clo,
    int Nc, int Kc, int doGelu) {
    extern __shared__ char smx[];
    __nv_bfloat16* sAhi = (__nv_bfloat16*)smx;
    __nv_bfloat16* sAlo = sAhi + 3*64*SSTR;
    __nv_bfloat16* sBhi = sAlo + 3*64*SSTR;
    __nv_bfloat16* sBlo = sBhi + 3*128*SSTR;

    const int tid = threadIdx.x, wid = tid >> 5, lane = tid & 31;
    const int g = lane >> 2, t2 = (lane & 3)*2;
    const int wm = (wid >> 2)*32, wn = (wid & 3)*32;
    const int m0 = blockIdx.y*64, n0 = blockIdx.x*128;

    const int ar = tid >> 2, ac = (tid & 3)*8;
    const int br0 = tid >> 2, bc0 = (tid & 3)*8;
    const int br1 = (tid + 256) >> 2, bc1 = ((tid + 256) & 3)*8;

    const int which = lane >> 3, rowin = lane & 7;
    uint32_t aoff[2], boff[2];
    #pragma unroll
    for (int i = 0; i < 2; i++)
        aoff[i] = ((wm + i*16 + (which & 1)*8 + rowin)*SSTR + (which >> 1)*8)*2;
    #pragma unroll
    for (int p = 0; p < 2; p++)
        boff[p] = ((wn + p*16 + (which >> 1)*8 + rowin)*SSTR + (which & 1)*8)*2;
    const uint32_t uAhi = smem_to_u32(sAhi), uAlo = smem_to_u32(sAlo);
    const uint32_t uBhi = smem_to_u32(sBhi), uBlo = smem_to_u32(sBlo);

    auto issue = [&](int c, int buf) {
        int kc = c*32;
        cpa16(&sAhi[buf*(64*SSTR) + ar*SSTR + ac], Ahi + (size_t)(m0 + ar)*Kc + kc + ac);
        cpa16(&sAlo[buf*(64*SSTR) + ar*SSTR + ac], Alo + (size_t)(m0 + ar)*Kc + kc + ac);
        cpa16(&sBhi[buf*(128*SSTR) + br0*SSTR + bc0], Bhi + (size_t)(n0 + br0)*Kc + kc + bc0);
        cpa16(&sBhi[buf*(128*SSTR) + br1*SSTR + bc1], Bhi + (size_t)(n0 + br1)*Kc + kc + bc1);
        cpa16(&sBlo[buf*(128*SSTR) + br0*SSTR + bc0], Blo + (size_t)(n0 + br0)*Kc + kc + bc0);
        cpa16(&sBlo[buf*(128*SSTR) + br1*SSTR + bc1], Blo + (size_t)(n0 + br1)*Kc + kc + bc1);
    };

    float acc[2][4][4] = {};
    const int nch = Kc >> 5;
    issue(0, 0); CP_COMMIT();
    issue(1, 1); CP_COMMIT();

    for (int c = 0; c < nch; c++) {
        int buf = c % 3;
        if (c + 2 < nch) {
            CP_WAIT(1);
            __syncthreads();
            issue(c + 2, (c + 2) % 3);
            CP_COMMIT();
        } else {
            CP_WAIT(0);
            __syncthreads();
        }
        const uint32_t offA = buf*(64*SSTR*2), offB = buf*(128*SSTR*2);
        #pragma unroll
        for (int ks = 0; ks < 32; ks += 16) {
            uint32_t ah[2][4], al[2][4], bh[8], bl[8];
            #pragma unroll
            for (int i = 0; i < 2; i++) {
                ldm_x4(ah[i], uAhi + offA + aoff[i] + ks*2);
                ldm_x4(al[i], uAlo + offA + aoff[i] + ks*2);
            }
            #pragma unroll
            for (int p = 0; p < 2; p++) {
                ldm_x4(&bh[p*4], uBhi + offB + boff[p] + ks*2);
                ldm_x4(&bl[p*4], uBlo + offB + boff[p] + ks*2);
            }
            #pragma unroll
            for (int i = 0; i < 2; i++)
                #pragma unroll
                for (int j = 0; j < 4; j++) {
                    mma16816(acc[i][j], ah[i], &bh[j*2]);
                    mma16816(acc[i][j], ah[i], &bl[j*2]);
                    mma16816(acc[i][j], al[i], &bh[j*2]);
                }
        }
    }

    #pragma unroll
    for (int i = 0; i < 2; i++) {
        int r0 = m0 + wm + i*16 + g;
        #pragma unroll
        for (int j = 0; j < 4; j++) {
            int col = n0 + wn + j*8 + t2;
            float b0 = bias[col], b1 = bias[col + 1];
            float2 v0 = { acc[i][j][0] + b0, acc[i][j][1] + b1 };
            float2 v1 = { acc[i][j][2] + b0, acc[i][j][3] + b1 };
            if (res) {
                float2 r0v = *(const float2*)&res[(size_t)r0*Nc + col];
                float2 r1v = *(const float2*)&res[(size_t)(r0 + 8)*Nc + col];
                v0.x += r0v.x; v0.y += r0v.y; v1.x += r1v.x; v1.y += r1v.y;
            }
            if (doGelu) {
                v0.x = 0.5f*v0.x*(1.f + erff(v0.x*0.70710678118654752f));
                v0.y = 0.5f*v0.y*(1.f + erff(v0.y*0.70710678118654752f));
                v1.x = 0.5f*v1.x*(1.f + erff(v1.x*0.70710678118654752f));
                v1.y = 0.5f*v1.y*(1.f + erff(v1.y*0.70710678118654752f));
            }
            if (Chi) {
                __nv_bfloat16 h00 = __float2bfloat16_rn(v0.x), h01 = __float2bfloat16_rn(v0.y);
                __nv_bfloat16 h10 = __float2bfloat16_rn(v1.x), h11 = __float2bfloat16_rn(v1.y);
                __nv_bfloat162 hp0(h00, h01), hp1(h10, h11);
                __nv_bfloat162 lp0(__float2bfloat16_rn(v0.x - bf2f(h00)), __float2bfloat16_rn(v0.y - bf2f(h01)));
                __nv_bfloat162 lp1(__float2bfloat16_rn(v1.x - bf2f(h10)), __float2bfloat16_rn(v1.y - bf2f(h11)));
                *(uint32_t*)&Chi[(size_t)r0*Nc + col]       = *(uint32_t*)&hp0;
                *(uint32_t*)&Chi[(size_t)(r0 + 8)*Nc + col] = *(uint32_t*)&hp1;
                *(uint32_t*)&Clo[(size_t)r0*Nc + col]       = *(uint32_t*)&lp0;
                *(uint32_t*)&Clo[(size_t)(r0 + 8)*Nc + col] = *(uint32_t*)&lp1;
            }
            if (Cf) {
                *(float2*)&Cf[(size_t)r0*Nc + col]       = v0;
                *(float2*)&Cf[(size_t)(r0 + 8)*Nc + col] = v1;
            }
        }
    }
}

// ---------------------------------------------------------------------------
extern "C" void kernel_launch(void* const* d_in, const int* in_sizes, int n_in,
                              void* d_out, int out_size) {
    const float* x     = (const float*)d_in[0];
    const float* coord = (const float*)d_in[1];
    const float* ln1_g = (const float*)d_in[2];
    const float* ln1_b = (const float*)d_in[3];
    const float* wq    = (const float*)d_in[4];
    const float* bq    = (const float*)d_in[5];
    const float* wk    = (const float*)d_in[6];
    const float* bk    = (const float*)d_in[7];
    const float* wv    = (const float*)d_in[8];
    const float* bv    = (const float*)d_in[9];
    const float* wo    = (const float*)d_in[10];
    const float* bo    = (const float*)d_in[11];
    const float* rel_k = (const float*)d_in[12];
    const float* rel_v = (const float*)d_in[13];
    const float* ln2_g = (const float*)d_in[14];
    const float* ln2_b = (const float*)d_in[15];
    const float* w1    = (const float*)d_in[16];
    const float* b1    = (const float*)d_in[17];
    const float* w2    = (const float*)d_in[18];
    const float* b2    = (const float*)d_in[19];
    const float* lnf_g = (const float*)d_in[20];
    const float* lnf_b = (const float*)d_in[21];

    float *px, *pbqkv;
    __nv_bfloat16 *pqkvhi, *pqkvlo, *phhi, *phlo, *pohi, *polo, *pfhi, *pflo, *pwhi, *pwlo;
    cudaGetSymbolAddress((void**)&px,     g_x);
    cudaGetSymbolAddress((void**)&pbqkv,  g_bqkv);
    cudaGetSymbolAddress((void**)&pqkvhi, g_qkvhi);
    cudaGetSymbolAddress((void**)&pqkvlo, g_qkvlo);
    cudaGetSymbolAddress((void**)&phhi,   g_hhi);
    cudaGetSymbolAddress((void**)&phlo,   g_hlo);
    cudaGetSymbolAddress((void**)&pohi,   g_ohi);
    cudaGetSymbolAddress((void**)&polo,   g_olo);
    cudaGetSymbolAddress((void**)&pfhi,   g_fhi);
    cudaGetSymbolAddress((void**)&pflo,   g_flo);
    cudaGetSymbolAddress((void**)&pwhi,   g_whi);
    cudaGetSymbolAddress((void**)&pwlo,   g_wlo);

    cudaFuncSetAttribute(gemm_mma_kernel, cudaFuncAttributeMaxDynamicSharedMemorySize, GSMEM_TOTAL);
    cudaFuncSetAttribute(attn_kernel, cudaFuncAttributeMaxDynamicSharedMemorySize, ASMEM_TOTAL);

    // Launch sequence: memcpy(1), setup(2), ln(3), qkv(4), attn(5) <- ncu capture
    cudaMemcpyAsync(px, x, sizeof(float)*TOK*Dd, cudaMemcpyDeviceToDevice);
    setup_all_kernel<<<dim3(16, 16, Ll*6 + 2), dim3(32, 8)>>>(
        wq, wk, wv, wo, w1, w2, bq, bk, bv, coord);

    const dim3 gQKV(12, 32);   // N=1536
    const dim3 gPRJ(4, 32);    // N=512
    const dim3 gFF1(16, 32);   // N=2048

    for (int l = 0; l < Ll; l++) {
        size_t lo = (size_t)l * WL_STRIDE;
        ln_kernel<<<TOK/8, 256>>>(px, ln1_g + l*Dd, ln1_b + l*Dd, phhi, phlo, nullptr);
        gemm_mma_kernel<<<gQKV, 256, GSMEM_TOTAL>>>(
            phhi, phlo, pwhi + lo, pwlo + lo, pbqkv + l*1536, nullptr,
            nullptr, pqkvhi, pqkvlo, 1536, 512, 0);
        attn_kernel<<<dim3(Nn/16, Hh, Bb), 256, ASMEM_TOTAL>>>(
            rel_k + (size_t)l*Kb*DHd, rel_v + (size_t)l*Kb*DHd);
        gemm_mma_kernel<<<gPRJ, 256, GSMEM_TOTAL>>>(
            pohi, polo, pwhi + lo + 786432, pwlo + lo + 786432, bo + l*Dd, px,
            px, nullptr, nullptr, 512, 512, 0);
        ln_kernel<<<TOK/8, 256>>>(px, ln2_g + l*Dd, ln2_b + l*Dd, phhi, phlo, nullptr);
        gemm_mma_kernel<<<gFF1, 256, GSMEM_TOTAL>>>(
            phhi, phlo, pwhi + lo + 1048576, pwlo + lo + 1048576, b1 + l*Mf, nullptr,
            nullptr, pfhi, pflo, 2048, 512, 1);
        gemm_mma_kernel<<<gPRJ, 256, GSMEM_TOTAL>>>(
            pfhi, pflo, pwhi + lo + 2097152, pwlo + lo + 2097152, b2 + l*Dd, px,
            px, nullptr, nullptr, 512, 2048, 0);
    }
    ln_kernel<<<TOK/8, 256>>>(px, lnf_g, lnf_b, nullptr, nullptr, (float*)d_out);
}

// round 16
// speedup vs baseline: 1.0842x; 1.0109x over previous
#include <cuda_runtime.h>
#include <cuda_bf16.h>
#include <cstdint>
#include <math.h>

// Problem constants
#define Bb   4
#define Nn   512
#define Dd   512
#define Hh   8
#define DHd  64
#define Kb   10
#define Mf   2048
#define Ll   4
#define TOK  (Bb*Nn)      // 2048
#define EPSf 1e-5f

// ---------------- scratch (device globals) ----------------------------------
__device__ float g_x[TOK*Dd];
__device__ unsigned char g_idx[Bb*Nn*Nn];
__device__ __nv_bfloat16 g_qkvhi[TOK*1536], g_qkvlo[TOK*1536];
__device__ __nv_bfloat16 g_hhi[TOK*Dd], g_hlo[TOK*Dd];
__device__ __nv_bfloat16 g_ohi[TOK*Dd], g_olo[TOK*Dd];
__device__ __nv_bfloat16 g_fhi[TOK*Mf], g_flo[TOK*Mf];
#define WL_STRIDE 3145728
__device__ __nv_bfloat16 g_whi[Ll*WL_STRIDE], g_wlo[Ll*WL_STRIDE];
__device__ float g_bqkv[Ll*1536];

// ---------------- helpers ----------------------------------------------------
__device__ __forceinline__ uint32_t smem_to_u32(const void* p) {
    uint32_t a;
    asm("{ .reg .u64 t; cvta.to.shared.u64 t, %1; cvt.u32.u64 %0, t; }"
        : "=r"(a) : "l"(p));
    return a;
}
__device__ __forceinline__ void cpa16(void* dst, const void* src) {
    uint32_t d = smem_to_u32(dst);
    asm volatile("cp.async.cg.shared.global [%0], [%1], 16;" :: "r"(d), "l"(src));
}
#define CP_COMMIT() asm volatile("cp.async.commit_group;" ::: "memory")
#define CP_WAIT(n)  asm volatile("cp.async.wait_group %0;" :: "n"(n) : "memory")

__device__ __forceinline__ void mma16816(float* c, const uint32_t* a, const uint32_t* b) {
    asm volatile("mma.sync.aligned.m16n8k16.row.col.f32.bf16.bf16.f32 "
        "{%0,%1,%2,%3}, {%4,%5,%6,%7}, {%8,%9}, {%0,%1,%2,%3};"
        : "+f"(c[0]), "+f"(c[1]), "+f"(c[2]), "+f"(c[3])
        : "r"(a[0]), "r"(a[1]), "r"(a[2]), "r"(a[3]), "r"(b[0]), "r"(b[1]));
}
__device__ __forceinline__ void ldm_x4(uint32_t* r, uint32_t addr) {
    asm volatile("ldmatrix.sync.aligned.m8n8.x4.shared.b16 {%0,%1,%2,%3}, [%4];"
        : "=r"(r[0]), "=r"(r[1]), "=r"(r[2]), "=r"(r[3]) : "r"(addr));
}
__device__ __forceinline__ void ldm_x4t(uint32_t* r, uint32_t addr) {
    asm volatile("ldmatrix.sync.aligned.m8n8.x4.trans.shared.b16 {%0,%1,%2,%3}, [%4];"
        : "=r"(r[0]), "=r"(r[1]), "=r"(r[2]), "=r"(r[3]) : "r"(addr));
}
__device__ __forceinline__ float bf2f(__nv_bfloat16 h) { return __bfloat162float(h); }

// FMA-pipe exp (rel err ~2e-6, x<=0)
__device__ __forceinline__ float fexp(float x) {
    float t = x * 1.4426950408889634f;
    float n = rintf(t);
    float f = t - n;
    float p = 1.3534581e-3f;
    p = fmaf(p, f, 9.6181291e-3f);
    p = fmaf(p, f, 5.5504109e-2f);
    p = fmaf(p, f, 2.4022651e-1f);
    p = fmaf(p, f, 6.9314718e-1f);
    p = fmaf(p, f, 1.0f);
    return p * __int_as_float(((int)n + 127) << 23);
}

// ---------------- setup: weights + bias pack + idx in ONE launch --------------
__global__ void setup_all_kernel(const float* __restrict__ wq, const float* __restrict__ wk,
                                 const float* __restrict__ wv, const float* __restrict__ wo,
                                 const float* __restrict__ w1, const float* __restrict__ w2,
                                 const float* __restrict__ bq, const float* __restrict__ bk,
                                 const float* __restrict__ bv, const float* __restrict__ coord) {
    __shared__ float t[32][33];
    int z = blockIdx.z;
    int tx = threadIdx.x, ty = threadIdx.y;
    int tid = ty*32 + tx;
    int bb = blockIdx.y*16 + blockIdx.x;

    if (z == Ll*6) {
        int i = bb*256 + tid;
        if (i < Ll*1536) {
            int l = i / 1536, c = i % 1536;
            g_bqkv[i] = (c < 512) ? bq[l*512 + c]
                      : (c < 1024 ? bk[l*512 + c - 512] : bv[l*512 + c - 1024]);
        }
        return;
    }
    if (z == Ll*6 + 1) {
        #pragma unroll
        for (int r = 0; r < 8; r++) {
            int row = bb*8 + r;
            int n = row & (Nn-1), b = row >> 9;
            float2 cn = ((const float2*)coord)[b*Nn + n];
            #pragma unroll
            for (int half = 0; half < 2; half++) {
                int m = tid + half*256;
                float2 cm = ((const float2*)coord)[b*Nn + m];
                float dx = cn.x - cm.x, dy = cn.y - cm.y;
                float dist = sqrtf(dx*dx + dy*dy);
                int j = (int)floorf(dist);
                j = j < 0 ? 0 : (j > Kb-1 ? Kb-1 : j);
                g_idx[((size_t)(b*Nn + n))*Nn + m] = (unsigned char)j;
            }
        }
        return;
    }

    int l = z / 6, job = z % 6;
    const float* W; int K, N; size_t off;
    switch (job) {
        case 0: W = wq + (size_t)l*Dd*Dd; K = 512;  N = 512;  off = 0;       break;
        case 1: W = wk + (size_t)l*Dd*Dd; K = 512;  N = 512;  off = 262144;  break;
        case 2: W = wv + (size_t)l*Dd*Dd; K = 512;  N = 512;  off = 524288;  break;
        case 3: W = wo + (size_t)l*Dd*Dd; K = 512;  N = 512;  off = 786432;  break;
        case 4: W = w1 + (size_t)l*Dd*Mf; K = 512;  N = 2048; off = 1048576; break;
        default:W = w2 + (size_t)l*Mf*Dd; K = 2048; N = 512;  off = 2097152; break;
    }
    __nv_bfloat16* dh = g_whi + (size_t)l*WL_STRIDE + off;
    __nv_bfloat16* dl = g_wlo + (size_t)l*WL_STRIDE + off;
    int reps = (job >= 4) ? 4 : 1;
    for (int r = 0; r < reps; r++) {
        int nn0, k0;
        if (job == 4)      { nn0 = (blockIdx.x + 16*r)*32; k0 = blockIdx.y*32; }
        else if (job == 5) { nn0 = blockIdx.x*32; k0 = (blockIdx.y + 16*r)*32; }
        else               { nn0 = blockIdx.x*32; k0 = blockIdx.y*32; }
        #pragma unroll
        for (int i = 0; i < 4; i++)
            t[ty + i*8][tx] = W[(size_t)(k0 + ty + i*8)*N + nn0 + tx];
        __syncthreads();
        #pragma unroll
        for (int i = 0; i < 4; i++) {
            int nl = ty + i*8;
            float v = t[tx][nl];
            __nv_bfloat16 hb = __float2bfloat16_rn(v);
            size_t o = (size_t)(nn0 + nl)*K + k0 + tx;
            dh[o] = hb; dl[o] = __float2bfloat16_rn(v - bf2f(hb));
        }
        __syncthreads();
    }
}

// ---------------- layernorm: warp per row, 8 rows/block ------------------------
__global__ __launch_bounds__(256) void ln_kernel(
    const float* __restrict__ x, const float* __restrict__ g, const float* __restrict__ b,
    __nv_bfloat16* __restrict__ ohi, __nv_bfloat16* __restrict__ olo,
    float* __restrict__ of) {
    int wid = threadIdx.x >> 5, lane = threadIdx.x & 31;
    int row = blockIdx.x*8 + wid;
    const float* xr = x + (size_t)row*Dd;
    float4 v[4];
    float sum = 0.f;
    #pragma unroll
    for (int w = 0; w < 4; w++) {
        v[w] = *(const float4*)&xr[w*128 + lane*4];
        sum += v[w].x + v[w].y + v[w].z + v[w].w;
    }
    #pragma unroll
    for (int o = 16; o > 0; o >>= 1) sum += __shfl_xor_sync(~0u, sum, o);
    float mean = sum * (1.0f / Dd);
    float var = 0.f;
    #pragma unroll
    for (int w = 0; w < 4; w++) {
        v[w].x -= mean; v[w].y -= mean; v[w].z -= mean; v[w].w -= mean;
        var += v[w].x*v[w].x + v[w].y*v[w].y + v[w].z*v[w].z + v[w].w*v[w].w;
    }
    #pragma unroll
    for (int o = 16; o > 0; o >>= 1) var += __shfl_xor_sync(~0u, var, o);
    float inv = rsqrtf(var * (1.0f / Dd) + EPSf);
    #pragma unroll
    for (int w = 0; w < 4; w++) {
        int idx = w*128 + lane*4;
        float4 gg = *(const float4*)&g[idx];
        float4 bb = *(const float4*)&b[idx];
        float y0 = v[w].x*inv*gg.x + bb.x, y1 = v[w].y*inv*gg.y + bb.y;
        float y2 = v[w].z*inv*gg.z + bb.z, y3 = v[w].w*inv*gg.w + bb.w;
        if (of) {
            float4 o4 = {y0, y1, y2, y3};
            *(float4*)&of[(size_t)row*Dd + idx] = o4;
        } else {
            __nv_bfloat16 h0 = __float2bfloat16_rn(y0), h1 = __float2bfloat16_rn(y1);
            __nv_bfloat16 h2 = __float2bfloat16_rn(y2), h3 = __float2bfloat16_rn(y3);
            __nv_bfloat162 hp0(h0, h1), hp1(h2, h3);
            __nv_bfloat162 lp0(__float2bfloat16_rn(y0 - bf2f(h0)), __float2bfloat16_rn(y1 - bf2f(h1)));
            __nv_bfloat162 lp1(__float2bfloat16_rn(y2 - bf2f(h2)), __float2bfloat16_rn(y3 - bf2f(h3)));
            uint2 uh = { *(uint32_t*)&hp0, *(uint32_t*)&hp1 };
            uint2 ul = { *(uint32_t*)&lp0, *(uint32_t*)&lp1 };
            *(uint2*)&ohi[(size_t)row*Dd + idx] = uh;
            *(uint2*)&olo[(size_t)row*Dd + idx] = ul;
        }
    }
}

// ---------------- fused attention: all-MMA scores + PV -------------------------
// Register-resident softmax; phase-1 K loads overlapped with score epilogue.
#define SCS 520
#define ASMEM_TOTAL 110080
__global__ __launch_bounds__(256, 2) void attn_kernel(const float* __restrict__ relk,
                                                      const float* __restrict__ relv) {
    extern __shared__ char smx[];
    __nv_bfloat16* khi = (__nv_bfloat16*)smx;
    __nv_bfloat16* klo = (__nv_bfloat16*)(smx + 18432);
    float* sc   = (float*)(smx + 36864);
    __nv_bfloat16* phh = (__nv_bfloat16*)(smx + 70144);
    __nv_bfloat16* pll = (__nv_bfloat16*)(smx + 86784);
    __nv_bfloat16* qhi = (__nv_bfloat16*)(smx + 103424);
    __nv_bfloat16* qlo = (__nv_bfloat16*)(smx + 105728);
    float* qrs  = (float*)(smx + 108032);
    float* pbin = (float*)(smx + 109056);

    const int tid = threadIdx.x, w = tid >> 5, lane = tid & 31;
    const int n0 = blockIdx.x*16, h = blockIdx.y, b = blockIdx.z;
    const size_t tokbase = (size_t)(b*Nn);

    {
        int tensor = tid >> 7, idx = tid & 127, r = idx >> 3, cg = idx & 7;
        const __nv_bfloat16* src = (tensor ? g_qkvlo : g_qkvhi)
            + (tokbase + n0 + r)*1536 + h*DHd + cg*8;
        __nv_bfloat16* dst = (tensor ? qlo : qhi) + r*72 + cg*8;
        *(uint4*)dst = *(const uint4*)src;
    }
    pbin[tid] = 0.f;
    for (int i = tid; i < 2048; i += 256) {
        int tensor = i >> 10, idx = i & 1023, r = idx >> 3, cg = idx & 7;
        const __nv_bfloat16* src = (tensor ? g_qkvlo : g_qkvhi)
            + (tokbase + r)*1536 + Dd + h*DHd + cg*8;
        __nv_bfloat16* dst = (tensor ? klo : khi) + r*72 + cg*8;
        cpa16(dst, src);
    }
    CP_COMMIT();
    __syncthreads();

    if (tid < 16*Kb) {
        int qi = tid / Kb, j = tid % Kb;
        float dot = 0.f;
        #pragma unroll
        for (int d = 0; d < DHd; d++)
            dot += (bf2f(qhi[qi*72 + d]) + bf2f(qlo[qi*72 + d])) * relk[j*64 + d];
        qrs[qi*16 + j] = dot;
    }

    const int which = lane >> 3, rowin = lane & 7;
    const uint32_t aoff = (((which & 1)*8 + rowin)*72 + (which >> 1)*8)*2;
    const uint32_t boff = ((w*16 + (which >> 1)*8 + rowin)*72 + (which & 1)*8)*2;
    const uint32_t uQhi = smem_to_u32(qhi), uQlo = smem_to_u32(qlo);
    const uint32_t uKhi = smem_to_u32(khi), uKlo = smem_to_u32(klo);
    const int g = lane >> 2, t2 = (lane & 3)*2;

    // ---- phase 1: scores; K(mc+1) load overlapped with epilogue ----
    CP_WAIT(0);
    __syncthreads();    // chunk 0 + qrs visible
    for (int mc = 0; mc < 4; mc++) {
        float acc[2][4] = {};
        #pragma unroll
        for (int ks = 0; ks < 4; ks++) {
            uint32_t qh4[4], ql4[4], kh4[4], kl4[4];
            ldm_x4(qh4, uQhi + aoff + ks*32);
            ldm_x4(ql4, uQlo + aoff + ks*32);
            ldm_x4(kh4, uKhi + boff + ks*32);
            ldm_x4(kl4, uKlo + boff + ks*32);
            #pragma unroll
            for (int j = 0; j < 2; j++) {
                mma16816(acc[j], qh4, &kh4[j*2]);
                mma16816(acc[j], qh4, &kl4[j*2]);
                mma16816(acc[j], ql4, &kh4[j*2]);
            }
        }
        __syncthreads();   // all warps done reading K buffer
        if (mc < 3) {
            for (int i = tid; i < 2048; i += 256) {
                int tensor = i >> 10, idx = i & 1023, r = idx >> 3, cg = idx & 7;
                const __nv_bfloat16* src = (tensor ? g_qkvlo : g_qkvhi)
                    + (tokbase + (mc + 1)*128 + r)*1536 + Dd + h*DHd + cg*8;
                __nv_bfloat16* dst = (tensor ? klo : khi) + r*72 + cg*8;
                cpa16(dst, src);
            }
            CP_COMMIT();
        }
        // epilogue overlaps the async load
        #pragma unroll
        for (int j = 0; j < 2; j++) {
            int m = mc*128 + w*16 + j*8 + t2;
            const unsigned char* ir0 = g_idx + (tokbase + n0 + g)*Nn + m;
            const unsigned char* ir1 = g_idx + (tokbase + n0 + g + 8)*Nn + m;
            sc[g*SCS + m]       = (acc[j][0] + qrs[g*16 + ir0[0]]) * 0.125f;
            sc[g*SCS + m + 1]   = (acc[j][1] + qrs[g*16 + ir0[1]]) * 0.125f;
            sc[(g+8)*SCS + m]   = (acc[j][2] + qrs[(g+8)*16 + ir1[0]]) * 0.125f;
            sc[(g+8)*SCS + m+1] = (acc[j][3] + qrs[(g+8)*16 + ir1[1]]) * 0.125f;
        }
        if (mc < 3) CP_WAIT(0);
        __syncthreads();
    }

    // prefetch V chunk 0 (overlaps softmax)
    for (int i = tid; i < 2048; i += 256) {
        int tensor = i >> 10, idx = i & 1023, r = idx >> 3, cg = idx & 7;
        const __nv_bfloat16* src = (tensor ? g_qkvlo : g_qkvhi)
            + (tokbase + r)*1536 + 2*Dd + h*DHd + cg*8;
        __nv_bfloat16* dst = (tensor ? klo : khi) + r*72 + cg*8;
        cpa16(dst, src);
    }
    CP_COMMIT();

    // ---- phase 2: register-resident softmax (warp per 2 rows) ----
    #pragma unroll
    for (int rr = 0; rr < 2; rr++) {
        int row = w*2 + rr;
        float rv[16];
        float mx = -1e30f;
        #pragma unroll
        for (int i = 0; i < 16; i++) {
            rv[i] = sc[row*SCS + lane + i*32];
            mx = fmaxf(mx, rv[i]);
        }
        #pragma unroll
        for (int o = 16; o > 0; o >>= 1) mx = fmaxf(mx, __shfl_xor_sync(~0u, mx, o));
        float sum = 0.f;
        #pragma unroll
        for (int i = 0; i < 16; i++) {
            rv[i] = fexp(rv[i] - mx);
            sum += rv[i];
        }
        #pragma unroll
        for (int o = 16; o > 0; o >>= 1) sum += __shfl_xor_sync(~0u, sum, o);
        float inv = 1.f / sum;
        float pb[Kb];
        #pragma unroll
        for (int j = 0; j < Kb; j++) pb[j] = 0.f;
        const unsigned char* ir = g_idx + (tokbase + n0 + row)*Nn;
        #pragma unroll
        for (int i = 0; i < 16; i++) {
            int m = lane + i*32;
            float p = rv[i] * inv;
            __nv_bfloat16 ph = __float2bfloat16_rn(p);
            phh[row*SCS + m] = ph;
            pll[row*SCS + m] = __float2bfloat16_rn(p - bf2f(ph));
            int ji = ir[m];
            #pragma unroll
            for (int j = 0; j < Kb; j++) if (ji == j) pb[j] += p;
        }
        #pragma unroll
        for (int j = 0; j < Kb; j++) {
            float v = pb[j];
            #pragma unroll
            for (int o = 16; o > 0; o >>= 1) v += __shfl_xor_sync(~0u, v, o);
            if (lane == 0) pbin[row*16 + j] = v;
        }
    }

    // ---- phase 3: P @ V via 3-term mma ----
    const int n0w = (w & 3)*16, khalf = w >> 2;
    const uint32_t uPh = smem_to_u32(phh), uPl = smem_to_u32(pll);
    const uint32_t paoff = (((which & 1)*8 + rowin)*SCS + (which >> 1)*8)*2;
    const uint32_t pboff = (((which & 1)*8 + rowin)*72 + n0w + (which >> 1)*8)*2;
    float c0[4] = {}, c1[4] = {};
    for (int mc = 0; mc < 4; mc++) {
        if (mc > 0) {
            for (int i = tid; i < 2048; i += 256) {
                int tensor = i >> 10, idx = i & 1023, r = idx >> 3, cg = idx & 7;
                const __nv_bfloat16* src = (tensor ? g_qkvlo : g_qkvhi)
                    + (tokbase + mc*128 + r)*1536 + 2*Dd + h*DHd + cg*8;
                __nv_bfloat16* dst = (tensor ? klo : khi) + r*72 + cg*8;
                cpa16(dst, src);
            }
            CP_COMMIT();
        }
        CP_WAIT(0);
        __syncthreads();
        #pragma unroll
        for (int ks = 0; ks < 4; ks++) {
            int kP = mc*128 + khalf*64 + ks*16;
            int kV = khalf*64 + ks*16;
            uint32_t ph4[4], pl4[4], vh4[4], vl4[4];
            ldm_x4(ph4, uPh + paoff + kP*2);
            ldm_x4(pl4, uPl + paoff + kP*2);
            ldm_x4t(vh4, uKhi + pboff + kV*144);
            ldm_x4t(vl4, uKlo + pboff + kV*144);
            mma16816(c0, ph4, &vh4[0]);
            mma16816(c0, ph4, &vl4[0]);
            mma16816(c0, pl4, &vh4[0]);
            mma16816(c1, ph4, &vh4[2]);
            mma16816(c1, ph4, &vl4[2]);
            mma16816(c1, pl4, &vh4[2]);
        }
        __syncthreads();
    }
    {
        float* outp = sc + khalf*(16*68);
        outp[g*68 + n0w + t2]          = c0[0];
        outp[g*68 + n0w + t2 + 1]      = c0[1];
        outp[(g+8)*68 + n0w + t2]      = c0[2];
        outp[(g+8)*68 + n0w + t2 + 1]  = c0[3];
        outp[g*68 + n0w + 8 + t2]      = c1[0];
        outp[g*68 + n0w + 8 + t2 + 1]  = c1[1];
        outp[(g+8)*68 + n0w + 8 + t2]  = c1[2];
        outp[(g+8)*68 + n0w + 8 + t2+1]= c1[3];
    }
    __syncthreads();
    for (int i = tid; i < 1024; i += 256) {
        int qi = i >> 6, d = i & 63;
        float o = sc[qi*68 + d] + sc[16*68 + qi*68 + d];
        #pragma unroll
        for (int j = 0; j < Kb; j++) o += pbin[qi*16 + j] * relv[j*64 + d];
        size_t tok = tokbase + n0 + qi;
        __nv_bfloat16 hb = __float2bfloat16_rn(o);
        g_ohi[tok*Dd + h*DHd + d] = hb;
        g_olo[tok*Dd + h*DHd + d] = __float2bfloat16_rn(o - bf2f(hb));
    }
}

// ---------------- bf16x3 mma GEMM, 3-stage cp.async + ldmatrix ----------------
// CTA 64(M)x128(N), BK=32, 256 thr, 8 warps 2x4 (warp 32x32).
#define SSTR 40
#define GSMEM_TOTAL 92160
__global__ __launch_bounds__(256, 2) void gemm_mma_kernel(
    const __nv_bfloat16* __restrict__ Ahi, const __nv_bfloat16* __restrict__ Alo,
    const __nv_bfloat16* __restrict__ Bhi, const __nv_bfloat16* __restrict__ Blo,
    const float* __restrict__ bias, const float* __restrict__ res,
    float* __restrict__ Cf, __nv_bfloat16* __restrict__ Chi, __nv_bfloat16* __restrict__ Clo,
    int Nc, int Kc, int doGelu) {
    extern __shared__ char smx[];
    __nv_bfloat16* sAhi = (__nv_bfloat16*)smx;
    __nv_bfloat16* sAlo = sAhi + 3*64*SSTR;
    __nv_bfloat16* sBhi = sAlo + 3*64*SSTR;
    __nv_bfloat16* sBlo = sBhi + 3*128*SSTR;

    const int tid = threadIdx.x, wid = tid >> 5, lane = tid & 31;
    const int g = lane >> 2, t2 = (lane & 3)*2;
    const int wm = (wid >> 2)*32, wn = (wid & 3)*32;
    const int m0 = blockIdx.y*64, n0 = blockIdx.x*128;

    const int ar = tid >> 2, ac = (tid & 3)*8;
    const int br0 = tid >> 2, bc0 = (tid & 3)*8;
    const int br1 = (tid + 256) >> 2, bc1 = ((tid + 256) & 3)*8;

    const int which = lane >> 3, rowin = lane & 7;
    uint32_t aoff[2], boff[2];
    #pragma unroll
    for (int i = 0; i < 2; i++)
        aoff[i] = ((wm + i*16 + (which & 1)*8 + rowin)*SSTR + (which >> 1)*8)*2;
    #pragma unroll
    for (int p = 0; p < 2; p++)
        boff[p] = ((wn + p*16 + (which >> 1)*8 + rowin)*SSTR + (which & 1)*8)*2;
    const uint32_t uAhi = smem_to_u32(sAhi), uAlo = smem_to_u32(sAlo);
    const uint32_t uBhi = smem_to_u32(sBhi), uBlo = smem_to_u32(sBlo);

    auto issue = [&](int c, int buf) {
        int kc = c*32;
        cpa16(&sAhi[buf*(64*SSTR) + ar*SSTR + ac], Ahi + (size_t)(m0 + ar)*Kc + kc + ac);
        cpa16(&sAlo[buf*(64*SSTR) + ar*SSTR + ac], Alo + (size_t)(m0 + ar)*Kc + kc + ac);
        cpa16(&sBhi[buf*(128*SSTR) + br0*SSTR + bc0], Bhi + (size_t)(n0 + br0)*Kc + kc + bc0);
        cpa16(&sBhi[buf*(128*SSTR) + br1*SSTR + bc1], Bhi + (size_t)(n0 + br1)*Kc + kc + bc1);
        cpa16(&sBlo[buf*(128*SSTR) + br0*SSTR + bc0], Blo + (size_t)(n0 + br0)*Kc + kc + bc0);
        cpa16(&sBlo[buf*(128*SSTR) + br1*SSTR + bc1], Blo + (size_t)(n0 + br1)*Kc + kc + bc1);
    };

    float acc[2][4][4] = {};
    const int nch = Kc >> 5;
    issue(0, 0); CP_COMMIT();
    issue(1, 1); CP_COMMIT();

    for (int c = 0; c < nch; c++) {
        int buf = c % 3;
        if (c + 2 < nch) {
            CP_WAIT(1);
            __syncthreads();
            issue(c + 2, (c + 2) % 3);
            CP_COMMIT();
        } else {
            CP_WAIT(0);
            __syncthreads();
        }
        const uint32_t offA = buf*(64*SSTR*2), offB = buf*(128*SSTR*2);
        #pragma unroll
        for (int ks = 0; ks < 32; ks += 16) {
            uint32_t ah[2][4], al[2][4], bh[8], bl[8];
            #pragma unroll
            for (int i = 0; i < 2; i++) {
                ldm_x4(ah[i], uAhi + offA + aoff[i] + ks*2);
                ldm_x4(al[i], uAlo + offA + aoff[i] + ks*2);
            }
            #pragma unroll
            for (int p = 0; p < 2; p++) {
                ldm_x4(&bh[p*4], uBhi + offB + boff[p] + ks*2);
                ldm_x4(&bl[p*4], uBlo + offB + boff[p] + ks*2);
            }
            #pragma unroll
            for (int i = 0; i < 2; i++)
                #pragma unroll
                for (int j = 0; j < 4; j++) {
                    mma16816(acc[i][j], ah[i], &bh[j*2]);
                    mma16816(acc[i][j], ah[i], &bl[j*2]);
                    mma16816(acc[i][j], al[i], &bh[j*2]);
                }
        }
    }

    #pragma unroll
    for (int i = 0; i < 2; i++) {
        int r0 = m0 + wm + i*16 + g;
        #pragma unroll
        for (int j = 0; j < 4; j++) {
            int col = n0 + wn + j*8 + t2;
            float b0 = bias[col], b1 = bias[col + 1];
            float2 v0 = { acc[i][j][0] + b0, acc[i][j][1] + b1 };
            float2 v1 = { acc[i][j][2] + b0, acc[i][j][3] + b1 };
            if (res) {
                float2 r0v = *(const float2*)&res[(size_t)r0*Nc + col];
                float2 r1v = *(const float2*)&res[(size_t)(r0 + 8)*Nc + col];
                v0.x += r0v.x; v0.y += r0v.y; v1.x += r1v.x; v1.y += r1v.y;
            }
            if (doGelu) {
                v0.x = 0.5f*v0.x*(1.f + erff(v0.x*0.70710678118654752f));
                v0.y = 0.5f*v0.y*(1.f + erff(v0.y*0.70710678118654752f));
                v1.x = 0.5f*v1.x*(1.f + erff(v1.x*0.70710678118654752f));
                v1.y = 0.5f*v1.y*(1.f + erff(v1.y*0.70710678118654752f));
            }
            if (Chi) {
                __nv_bfloat16 h00 = __float2bfloat16_rn(v0.x), h01 = __float2bfloat16_rn(v0.y);
                __nv_bfloat16 h10 = __float2bfloat16_rn(v1.x), h11 = __float2bfloat16_rn(v1.y);
                __nv_bfloat162 hp0(h00, h01), hp1(h10, h11);
                __nv_bfloat162 lp0(__float2bfloat16_rn(v0.x - bf2f(h00)), __float2bfloat16_rn(v0.y - bf2f(h01)));
                __nv_bfloat162 lp1(__float2bfloat16_rn(v1.x - bf2f(h10)), __float2bfloat16_rn(v1.y - bf2f(h11)));
                *(uint32_t*)&Chi[(size_t)r0*Nc + col]       = *(uint32_t*)&hp0;
                *(uint32_t*)&Chi[(size_t)(r0 + 8)*Nc + col] = *(uint32_t*)&hp1;
                *(uint32_t*)&Clo[(size_t)r0*Nc + col]       = *(uint32_t*)&lp0;
                *(uint32_t*)&Clo[(size_t)(r0 + 8)*Nc + col] = *(uint32_t*)&lp1;
            }
            if (Cf) {
                *(float2*)&Cf[(size_t)r0*Nc + col]       = v0;
                *(float2*)&Cf[(size_t)(r0 + 8)*Nc + col] = v1;
            }
        }
    }
}

// ---------------------------------------------------------------------------
extern "C" void kernel_launch(void* const* d_in, const int* in_sizes, int n_in,
                              void* d_out, int out_size) {
    const float* x     = (const float*)d_in[0];
    const float* coord = (const float*)d_in[1];
    const float* ln1_g = (const float*)d_in[2];
    const float* ln1_b = (const float*)d_in[3];
    const float* wq    = (const float*)d_in[4];
    const float* bq    = (const float*)d_in[5];
    const float* wk    = (const float*)d_in[6];
    const float* bk    = (const float*)d_in[7];
    const float* wv    = (const float*)d_in[8];
    const float* bv    = (const float*)d_in[9];
    const float* wo    = (const float*)d_in[10];
    const float* bo    = (const float*)d_in[11];
    const float* rel_k = (const float*)d_in[12];
    const float* rel_v = (const float*)d_in[13];
    const float* ln2_g = (const float*)d_in[14];
    const float* ln2_b = (const float*)d_in[15];
    const float* w1    = (const float*)d_in[16];
    const float* b1    = (const float*)d_in[17];
    const float* w2    = (const float*)d_in[18];
    const float* b2    = (const float*)d_in[19];
    const float* lnf_g = (const float*)d_in[20];
    const float* lnf_b = (const float*)d_in[21];

    float *px, *pbqkv;
    __nv_bfloat16 *pqkvhi, *pqkvlo, *phhi, *phlo, *pohi, *polo, *pfhi, *pflo, *pwhi, *pwlo;
    cudaGetSymbolAddress((void**)&px,     g_x);
    cudaGetSymbolAddress((void**)&pbqkv,  g_bqkv);
    cudaGetSymbolAddress((void**)&pqkvhi, g_qkvhi);
    cudaGetSymbolAddress((void**)&pqkvlo, g_qkvlo);
    cudaGetSymbolAddress((void**)&phhi,   g_hhi);
    cudaGetSymbolAddress((void**)&phlo,   g_hlo);
    cudaGetSymbolAddress((void**)&pohi,   g_ohi);
    cudaGetSymbolAddress((void**)&polo,   g_olo);
    cudaGetSymbolAddress((void**)&pfhi,   g_fhi);
    cudaGetSymbolAddress((void**)&pflo,   g_flo);
    cudaGetSymbolAddress((void**)&pwhi,   g_whi);
    cudaGetSymbolAddress((void**)&pwlo,   g_wlo);

    cudaFuncSetAttribute(gemm_mma_kernel, cudaFuncAttributeMaxDynamicSharedMemorySize, GSMEM_TOTAL);
    cudaFuncSetAttribute(attn_kernel, cudaFuncAttributeMaxDynamicSharedMemorySize, ASMEM_TOTAL);

    // Launch sequence: memcpy(1), setup(2), ln(3), qkv(4), attn(5) <- ncu capture
    cudaMemcpyAsync(px, x, sizeof(float)*TOK*Dd, cudaMemcpyDeviceToDevice);
    setup_all_kernel<<<dim3(16, 16, Ll*6 + 2), dim3(32, 8)>>>(
        wq, wk, wv, wo, w1, w2, bq, bk, bv, coord);

    const dim3 gQKV(12, 32);   // N=1536
    const dim3 gPRJ(4, 32);    // N=512
    const dim3 gFF1(16, 32);   // N=2048

    for (int l = 0; l < Ll; l++) {
        size_t lo = (size_t)l * WL_STRIDE;
        ln_kernel<<<TOK/8, 256>>>(px, ln1_g + l*Dd, ln1_b + l*Dd, phhi, phlo, nullptr);
        gemm_mma_kernel<<<gQKV, 256, GSMEM_TOTAL>>>(
            phhi, phlo, pwhi + lo, pwlo + lo, pbqkv + l*1536, nullptr,
            nullptr, pqkvhi, pqkvlo, 1536, 512, 0);
        attn_kernel<<<dim3(Nn/16, Hh, Bb), 256, ASMEM_TOTAL>>>(
            rel_k + (size_t)l*Kb*DHd, rel_v + (size_t)l*Kb*DHd);
        gemm_mma_kernel<<<gPRJ, 256, GSMEM_TOTAL>>>(
            pohi, polo, pwhi + lo + 786432, pwlo + lo + 786432, bo + l*Dd, px,
            px, nullptr, nullptr, 512, 512, 0);
        ln_kernel<<<TOK/8, 256>>>(px, ln2_g + l*Dd, ln2_b + l*Dd, phhi, phlo, nullptr);
        gemm_mma_kernel<<<gFF1, 256, GSMEM_TOTAL>>>(
            phhi, phlo, pwhi + lo + 1048576, pwlo + lo + 1048576, b1 + l*Mf, nullptr,
            nullptr, pfhi, pflo, 2048, 512, 1);
        gemm_mma_kernel<<<gPRJ, 256, GSMEM_TOTAL>>>(
            pfhi, pflo, pwhi + lo + 2097152, pwlo + lo + 2097152, b2 + l*Dd, px,
            px, nullptr, nullptr, 512, 2048, 0);
    }
    ln_kernel<<<TOK/8, 256>>>(px, lnf_g, lnf_b, nullptr, nullptr, (float*)d_out);
}

// round 17
// speedup vs baseline: 1.0902x; 1.0055x over previous
#include <cuda_runtime.h>
#include <cuda_bf16.h>
#include <cstdint>
#include <math.h>

// Problem constants
#define Bb   4
#define Nn   512
#define Dd   512
#define Hh   8
#define DHd  64
#define Kb   10
#define Mf   2048
#define Ll   4
#define TOK  (Bb*Nn)      // 2048
#define EPSf 1e-5f

// ---------------- scratch (device globals) ----------------------------------
__device__ float g_x[TOK*Dd];
__device__ unsigned char g_idx[Bb*Nn*Nn];
__device__ __nv_bfloat16 g_qkvhi[TOK*1536], g_qkvlo[TOK*1536];
__device__ __nv_bfloat16 g_hhi[TOK*Dd], g_hlo[TOK*Dd];
__device__ __nv_bfloat16 g_ohi[TOK*Dd], g_olo[TOK*Dd];
__device__ __nv_bfloat16 g_fhi[TOK*Mf], g_flo[TOK*Mf];
#define WL_STRIDE 3145728
__device__ __nv_bfloat16 g_whi[Ll*WL_STRIDE], g_wlo[Ll*WL_STRIDE];
__device__ float g_bqkv[Ll*1536];

// ---------------- helpers ----------------------------------------------------
__device__ __forceinline__ uint32_t smem_to_u32(const void* p) {
    uint32_t a;
    asm("{ .reg .u64 t; cvta.to.shared.u64 t, %1; cvt.u32.u64 %0, t; }"
        : "=r"(a) : "l"(p));
    return a;
}
__device__ __forceinline__ void cpa16(void* dst, const void* src) {
    uint32_t d = smem_to_u32(dst);
    asm volatile("cp.async.cg.shared.global [%0], [%1], 16;" :: "r"(d), "l"(src));
}
#define CP_COMMIT() asm volatile("cp.async.commit_group;" ::: "memory")
#define CP_WAIT(n)  asm volatile("cp.async.wait_group %0;" :: "n"(n) : "memory")

__device__ __forceinline__ void mma16816(float* c, const uint32_t* a, const uint32_t* b) {
    asm volatile("mma.sync.aligned.m16n8k16.row.col.f32.bf16.bf16.f32 "
        "{%0,%1,%2,%3}, {%4,%5,%6,%7}, {%8,%9}, {%0,%1,%2,%3};"
        : "+f"(c[0]), "+f"(c[1]), "+f"(c[2]), "+f"(c[3])
        : "r"(a[0]), "r"(a[1]), "r"(a[2]), "r"(a[3]), "r"(b[0]), "r"(b[1]));
}
__device__ __forceinline__ void ldm_x4(uint32_t* r, uint32_t addr) {
    asm volatile("ldmatrix.sync.aligned.m8n8.x4.shared.b16 {%0,%1,%2,%3}, [%4];"
        : "=r"(r[0]), "=r"(r[1]), "=r"(r[2]), "=r"(r[3]) : "r"(addr));
}
__device__ __forceinline__ void ldm_x4t(uint32_t* r, uint32_t addr) {
    asm volatile("ldmatrix.sync.aligned.m8n8.x4.trans.shared.b16 {%0,%1,%2,%3}, [%4];"
        : "=r"(r[0]), "=r"(r[1]), "=r"(r[2]), "=r"(r[3]) : "r"(addr));
}
__device__ __forceinline__ float bf2f(__nv_bfloat16 h) { return __bfloat162float(h); }

// FMA-pipe exp (rel err ~2e-6, x<=0)
__device__ __forceinline__ float fexp(float x) {
    float t = x * 1.4426950408889634f;
    float n = rintf(t);
    float f = t - n;
    float p = 1.3534581e-3f;
    p = fmaf(p, f, 9.6181291e-3f);
    p = fmaf(p, f, 5.5504109e-2f);
    p = fmaf(p, f, 2.4022651e-1f);
    p = fmaf(p, f, 6.9314718e-1f);
    p = fmaf(p, f, 1.0f);
    return p * __int_as_float(((int)n + 127) << 23);
}

// ---------------- setup: weights + bias pack + idx in ONE launch --------------
__global__ void setup_all_kernel(const float* __restrict__ wq, const float* __restrict__ wk,
                                 const float* __restrict__ wv, const float* __restrict__ wo,
                                 const float* __restrict__ w1, const float* __restrict__ w2,
                                 const float* __restrict__ bq, const float* __restrict__ bk,
                                 const float* __restrict__ bv, const float* __restrict__ coord) {
    __shared__ float t[32][33];
    int z = blockIdx.z;
    int tx = threadIdx.x, ty = threadIdx.y;
    int tid = ty*32 + tx;
    int bb = blockIdx.y*16 + blockIdx.x;

    if (z == Ll*6) {
        int i = bb*256 + tid;
        if (i < Ll*1536) {
            int l = i / 1536, c = i % 1536;
            g_bqkv[i] = (c < 512) ? bq[l*512 + c]
                      : (c < 1024 ? bk[l*512 + c - 512] : bv[l*512 + c - 1024]);
        }
        return;
    }
    if (z == Ll*6 + 1) {
        #pragma unroll
        for (int r = 0; r < 8; r++) {
            int row = bb*8 + r;
            int n = row & (Nn-1), b = row >> 9;
            float2 cn = ((const float2*)coord)[b*Nn + n];
            #pragma unroll
            for (int half = 0; half < 2; half++) {
                int m = tid + half*256;
                float2 cm = ((const float2*)coord)[b*Nn + m];
                float dx = cn.x - cm.x, dy = cn.y - cm.y;
                float dist = sqrtf(dx*dx + dy*dy);
                int j = (int)floorf(dist);
                j = j < 0 ? 0 : (j > Kb-1 ? Kb-1 : j);
                g_idx[((size_t)(b*Nn + n))*Nn + m] = (unsigned char)j;
            }
        }
        return;
    }

    int l = z / 6, job = z % 6;
    const float* W; int K, N; size_t off;
    switch (job) {
        case 0: W = wq + (size_t)l*Dd*Dd; K = 512;  N = 512;  off = 0;       break;
        case 1: W = wk + (size_t)l*Dd*Dd; K = 512;  N = 512;  off = 262144;  break;
        case 2: W = wv + (size_t)l*Dd*Dd; K = 512;  N = 512;  off = 524288;  break;
        case 3: W = wo + (size_t)l*Dd*Dd; K = 512;  N = 512;  off = 786432;  break;
        case 4: W = w1 + (size_t)l*Dd*Mf; K = 512;  N = 2048; off = 1048576; break;
        default:W = w2 + (size_t)l*Mf*Dd; K = 2048; N = 512;  off = 2097152; break;
    }
    __nv_bfloat16* dh = g_whi + (size_t)l*WL_STRIDE + off;
    __nv_bfloat16* dl = g_wlo + (size_t)l*WL_STRIDE + off;
    int reps = (job >= 4) ? 4 : 1;
    for (int r = 0; r < reps; r++) {
        int nn0, k0;
        if (job == 4)      { nn0 = (blockIdx.x + 16*r)*32; k0 = blockIdx.y*32; }
        else if (job == 5) { nn0 = blockIdx.x*32; k0 = (blockIdx.y + 16*r)*32; }
        else               { nn0 = blockIdx.x*32; k0 = blockIdx.y*32; }
        #pragma unroll
        for (int i = 0; i < 4; i++)
            t[ty + i*8][tx] = W[(size_t)(k0 + ty + i*8)*N + nn0 + tx];
        __syncthreads();
        #pragma unroll
        for (int i = 0; i < 4; i++) {
            int nl = ty + i*8;
            float v = t[tx][nl];
            __nv_bfloat16 hb = __float2bfloat16_rn(v);
            size_t o = (size_t)(nn0 + nl)*K + k0 + tx;
            dh[o] = hb; dl[o] = __float2bfloat16_rn(v - bf2f(hb));
        }
        __syncthreads();
    }
}

// ---------------- layernorm: warp per row, 8 rows/block ------------------------
__global__ __launch_bounds__(256) void ln_kernel(
    const float* __restrict__ x, const float* __restrict__ g, const float* __restrict__ b,
    __nv_bfloat16* __restrict__ ohi, __nv_bfloat16* __restrict__ olo,
    float* __restrict__ of) {
    int wid = threadIdx.x >> 5, lane = threadIdx.x & 31;
    int row = blockIdx.x*8 + wid;
    const float* xr = x + (size_t)row*Dd;
    float4 v[4];
    float sum = 0.f;
    #pragma unroll
    for (int w = 0; w < 4; w++) {
        v[w] = *(const float4*)&xr[w*128 + lane*4];
        sum += v[w].x + v[w].y + v[w].z + v[w].w;
    }
    #pragma unroll
    for (int o = 16; o > 0; o >>= 1) sum += __shfl_xor_sync(~0u, sum, o);
    float mean = sum * (1.0f / Dd);
    float var = 0.f;
    #pragma unroll
    for (int w = 0; w < 4; w++) {
        v[w].x -= mean; v[w].y -= mean; v[w].z -= mean; v[w].w -= mean;
        var += v[w].x*v[w].x + v[w].y*v[w].y + v[w].z*v[w].z + v[w].w*v[w].w;
    }
    #pragma unroll
    for (int o = 16; o > 0; o >>= 1) var += __shfl_xor_sync(~0u, var, o);
    float inv = rsqrtf(var * (1.0f / Dd) + EPSf);
    #pragma unroll
    for (int w = 0; w < 4; w++) {
        int idx = w*128 + lane*4;
        float4 gg = *(const float4*)&g[idx];
        float4 bb = *(const float4*)&b[idx];
        float y0 = v[w].x*inv*gg.x + bb.x, y1 = v[w].y*inv*gg.y + bb.y;
        float y2 = v[w].z*inv*gg.z + bb.z, y3 = v[w].w*inv*gg.w + bb.w;
        if (of) {
            float4 o4 = {y0, y1, y2, y3};
            *(float4*)&of[(size_t)row*Dd + idx] = o4;
        } else {
            __nv_bfloat16 h0 = __float2bfloat16_rn(y0), h1 = __float2bfloat16_rn(y1);
            __nv_bfloat16 h2 = __float2bfloat16_rn(y2), h3 = __float2bfloat16_rn(y3);
            __nv_bfloat162 hp0(h0, h1), hp1(h2, h3);
            __nv_bfloat162 lp0(__float2bfloat16_rn(y0 - bf2f(h0)), __float2bfloat16_rn(y1 - bf2f(h1)));
            __nv_bfloat162 lp1(__float2bfloat16_rn(y2 - bf2f(h2)), __float2bfloat16_rn(y3 - bf2f(h3)));
            uint2 uh = { *(uint32_t*)&hp0, *(uint32_t*)&hp1 };
            uint2 ul = { *(uint32_t*)&lp0, *(uint32_t*)&lp1 };
            *(uint2*)&ohi[(size_t)row*Dd + idx] = uh;
            *(uint2*)&olo[(size_t)row*Dd + idx] = ul;
        }
    }
}

// ---------------- fused attention: all-MMA scores + PV -------------------------
// smem layout (bytes):
//   A:      0 kbuf/V-even: khi @0, klo @18432                 (36864)
//   B:  36864 sc f32 [16][520] (phases 1-2) / V-odd buffer    (36864)
//   C:  73728 phh (16640) | 90368 pll (16640)
//   D: 107008 qhi (2304)  | 109312 qlo (2304)
//   E: 111616 qrs (1024)  | 112640 pbin (1024)   -> total 113664 (2 CTAs/SM)
#define SCS 520
#define ASMEM_TOTAL 113664
__global__ __launch_bounds__(256, 2) void attn_kernel(const float* __restrict__ relk,
                                                      const float* __restrict__ relv) {
    extern __shared__ char smx[];
    __nv_bfloat16* khi = (__nv_bfloat16*)smx;
    __nv_bfloat16* klo = (__nv_bfloat16*)(smx + 18432);
    __nv_bfloat16* vh1 = (__nv_bfloat16*)(smx + 36864);
    __nv_bfloat16* vl1 = (__nv_bfloat16*)(smx + 55296);
    float* sc   = (float*)(smx + 36864);
    __nv_bfloat16* phh = (__nv_bfloat16*)(smx + 73728);
    __nv_bfloat16* pll = (__nv_bfloat16*)(smx + 90368);
    __nv_bfloat16* qhi = (__nv_bfloat16*)(smx + 107008);
    __nv_bfloat16* qlo = (__nv_bfloat16*)(smx + 109312);
    float* qrs  = (float*)(smx + 111616);
    float* pbin = (float*)(smx + 112640);

    const int tid = threadIdx.x, w = tid >> 5, lane = tid & 31;
    const int n0 = blockIdx.x*16, h = blockIdx.y, b = blockIdx.z;
    const size_t tokbase = (size_t)(b*Nn);

    {
        int tensor = tid >> 7, idx = tid & 127, r = idx >> 3, cg = idx & 7;
        const __nv_bfloat16* src = (tensor ? g_qkvlo : g_qkvhi)
            + (tokbase + n0 + r)*1536 + h*DHd + cg*8;
        __nv_bfloat16* dst = (tensor ? qlo : qhi) + r*72 + cg*8;
        *(uint4*)dst = *(const uint4*)src;
    }
    pbin[tid] = 0.f;
    for (int i = tid; i < 2048; i += 256) {
        int tensor = i >> 10, idx = i & 1023, r = idx >> 3, cg = idx & 7;
        const __nv_bfloat16* src = (tensor ? g_qkvlo : g_qkvhi)
            + (tokbase + r)*1536 + Dd + h*DHd + cg*8;
        __nv_bfloat16* dst = (tensor ? klo : khi) + r*72 + cg*8;
        cpa16(dst, src);
    }
    CP_COMMIT();
    __syncthreads();

    if (tid < 16*Kb) {
        int qi = tid / Kb, j = tid % Kb;
        float dot = 0.f;
        #pragma unroll
        for (int d = 0; d < DHd; d++)
            dot += (bf2f(qhi[qi*72 + d]) + bf2f(qlo[qi*72 + d])) * relk[j*64 + d];
        qrs[qi*16 + j] = dot;
    }

    const int which = lane >> 3, rowin = lane & 7;
    const uint32_t aoff = (((which & 1)*8 + rowin)*72 + (which >> 1)*8)*2;
    const uint32_t boff = ((w*16 + (which >> 1)*8 + rowin)*72 + (which & 1)*8)*2;
    const uint32_t uQhi = smem_to_u32(qhi), uQlo = smem_to_u32(qlo);
    const uint32_t uKhi = smem_to_u32(khi), uKlo = smem_to_u32(klo);
    const uint32_t uV1hi = smem_to_u32(vh1), uV1lo = smem_to_u32(vl1);
    const int g = lane >> 2, t2 = (lane & 3)*2;

    // ---- phase 1: scores; K(mc+1) load overlapped with epilogue ----
    CP_WAIT(0);
    __syncthreads();
    for (int mc = 0; mc < 4; mc++) {
        float acc[2][4] = {};
        #pragma unroll
        for (int ks = 0; ks < 4; ks++) {
            uint32_t qh4[4], ql4[4], kh4[4], kl4[4];
            ldm_x4(qh4, uQhi + aoff + ks*32);
            ldm_x4(ql4, uQlo + aoff + ks*32);
            ldm_x4(kh4, uKhi + boff + ks*32);
            ldm_x4(kl4, uKlo + boff + ks*32);
            #pragma unroll
            for (int j = 0; j < 2; j++) {
                mma16816(acc[j], qh4, &kh4[j*2]);
                mma16816(acc[j], qh4, &kl4[j*2]);
                mma16816(acc[j], ql4, &kh4[j*2]);
            }
        }
        __syncthreads();
        if (mc < 3) {
            for (int i = tid; i < 2048; i += 256) {
                int tensor = i >> 10, idx = i & 1023, r = idx >> 3, cg = idx & 7;
                const __nv_bfloat16* src = (tensor ? g_qkvlo : g_qkvhi)
                    + (tokbase + (mc + 1)*128 + r)*1536 + Dd + h*DHd + cg*8;
                __nv_bfloat16* dst = (tensor ? klo : khi) + r*72 + cg*8;
                cpa16(dst, src);
            }
            CP_COMMIT();
        }
        #pragma unroll
        for (int j = 0; j < 2; j++) {
            int m = mc*128 + w*16 + j*8 + t2;
            const unsigned char* ir0 = g_idx + (tokbase + n0 + g)*Nn + m;
            const unsigned char* ir1 = g_idx + (tokbase + n0 + g + 8)*Nn + m;
            sc[g*SCS + m]       = (acc[j][0] + qrs[g*16 + ir0[0]]) * 0.125f;
            sc[g*SCS + m + 1]   = (acc[j][1] + qrs[g*16 + ir0[1]]) * 0.125f;
            sc[(g+8)*SCS + m]   = (acc[j][2] + qrs[(g+8)*16 + ir1[0]]) * 0.125f;
            sc[(g+8)*SCS + m+1] = (acc[j][3] + qrs[(g+8)*16 + ir1[1]]) * 0.125f;
        }
        if (mc < 3) CP_WAIT(0);
        __syncthreads();
    }

    // ---- phase 2: register-resident softmax (warp per 2 rows) ----
    // (V chunk 0 prefetch into A happens after sc is consumed into registers;
    //  issued inside the per-row loop below, before heavy compute, by all threads)
    float rvreg[2][16];
    #pragma unroll
    for (int rr = 0; rr < 2; rr++) {
        int row = w*2 + rr;
        #pragma unroll
        for (int i = 0; i < 16; i++) rvreg[rr][i] = sc[row*SCS + lane + i*32];
    }
    __syncthreads();   // sc fully consumed; B region is now free for V-odd
    // prefetch V chunk 0 -> A (overlaps softmax)
    for (int i = tid; i < 2048; i += 256) {
        int tensor = i >> 10, idx = i & 1023, r = idx >> 3, cg = idx & 7;
        const __nv_bfloat16* src = (tensor ? g_qkvlo : g_qkvhi)
            + (tokbase + r)*1536 + 2*Dd + h*DHd + cg*8;
        __nv_bfloat16* dst = (tensor ? klo : khi) + r*72 + cg*8;
        cpa16(dst, src);
    }
    CP_COMMIT();
    // prefetch V chunk 1 -> B (also overlaps softmax)
    for (int i = tid; i < 2048; i += 256) {
        int tensor = i >> 10, idx = i & 1023, r = idx >> 3, cg = idx & 7;
        const __nv_bfloat16* src = (tensor ? g_qkvlo : g_qkvhi)
            + (tokbase + 128 + r)*1536 + 2*Dd + h*DHd + cg*8;
        __nv_bfloat16* dst = (tensor ? vl1 : vh1) + r*72 + cg*8;
        cpa16(dst, src);
    }
    CP_COMMIT();

    #pragma unroll
    for (int rr = 0; rr < 2; rr++) {
        int row = w*2 + rr;
        float* rv = rvreg[rr];
        float mx = -1e30f;
        #pragma unroll
        for (int i = 0; i < 16; i++) mx = fmaxf(mx, rv[i]);
        #pragma unroll
        for (int o = 16; o > 0; o >>= 1) mx = fmaxf(mx, __shfl_xor_sync(~0u, mx, o));
        float sum = 0.f;
        #pragma unroll
        for (int i = 0; i < 16; i++) {
            rv[i] = fexp(rv[i] - mx);
            sum += rv[i];
        }
        #pragma unroll
        for (int o = 16; o > 0; o >>= 1) sum += __shfl_xor_sync(~0u, sum, o);
        float inv = 1.f / sum;
        float pb[Kb];
        #pragma unroll
        for (int j = 0; j < Kb; j++) pb[j] = 0.f;
        const unsigned char* ir = g_idx + (tokbase + n0 + row)*Nn;
        #pragma unroll
        for (int i = 0; i < 16; i++) {
            int m = lane + i*32;
            float p = rv[i] * inv;
            __nv_bfloat16 ph = __float2bfloat16_rn(p);
            phh[row*SCS + m] = ph;
            pll[row*SCS + m] = __float2bfloat16_rn(p - bf2f(ph));
            int ji = ir[m];
            #pragma unroll
            for (int j = 0; j < Kb; j++) if (ji == j) pb[j] += p;
        }
        #pragma unroll
        for (int j = 0; j < Kb; j++) {
            float v = pb[j];
            #pragma unroll
            for (int o = 16; o > 0; o >>= 1) v += __shfl_xor_sync(~0u, v, o);
            if (lane == 0) pbin[row*16 + j] = v;
        }
    }

    // ---- phase 3: P @ V via 3-term mma, double-buffered V (A even / B odd) ----
    const int n0w = (w & 3)*16, khalf = w >> 2;
    const uint32_t uPh = smem_to_u32(phh), uPl = smem_to_u32(pll);
    const uint32_t paoff = (((which & 1)*8 + rowin)*SCS + (which >> 1)*8)*2;
    const uint32_t pboff = (((which & 1)*8 + rowin)*72 + n0w + (which >> 1)*8)*2;
    float c0[4] = {}, c1[4] = {};
    CP_WAIT(1);           // V0 ready (V1 may still be in flight)
    __syncthreads();      // phh/pll + V0 visible to all
    for (int mc = 0; mc < 4; mc++) {
        const uint32_t uVhi = (mc & 1) ? uV1hi : uKhi;
        const uint32_t uVlo = (mc & 1) ? uV1lo : uKlo;
        #pragma unroll
        for (int ks = 0; ks < 4; ks++) {
            int kP = mc*128 + khalf*64 + ks*16;
            int kV = khalf*64 + ks*16;
            uint32_t ph4[4], pl4[4], vh4[4], vl4[4];
            ldm_x4(ph4, uPh + paoff + kP*2);
            ldm_x4(pl4, uPl + paoff + kP*2);
            ldm_x4t(vh4, uVhi + pboff + kV*144);
            ldm_x4t(vl4, uVlo + pboff + kV*144);
            mma16816(c0, ph4, &vh4[0]);
            mma16816(c0, ph4, &vl4[0]);
            mma16816(c0, pl4, &vh4[0]);
            mma16816(c1, ph4, &vh4[2]);
            mma16816(c1, ph4, &vl4[2]);
            mma16816(c1, pl4, &vh4[2]);
        }
        __syncthreads();   // all warps done reading this buffer
        if (mc + 2 < 4) {
            // load V(mc+2) into the buffer just freed (same parity)
            __nv_bfloat16* dh = (mc & 1) ? vh1 : khi;
            __nv_bfloat16* dl = (mc & 1) ? vl1 : klo;
            for (int i = tid; i < 2048; i += 256) {
                int tensor = i >> 10, idx = i & 1023, r = idx >> 3, cg = idx & 7;
                const __nv_bfloat16* src = (tensor ? g_qkvlo : g_qkvhi)
                    + (tokbase + (mc + 2)*128 + r)*1536 + 2*Dd + h*DHd + cg*8;
                __nv_bfloat16* dst = (tensor ? dl : dh) + r*72 + cg*8;
                cpa16(dst, src);
            }
            CP_COMMIT();
        }
        if (mc < 3) {
            if (mc + 2 < 4) CP_WAIT(1); else CP_WAIT(0);   // V(mc+1) ready
            __syncthreads();
        }
    }

    // stage partials into A (dead after mc=2) and combine
    {
        float* outp = (float*)smx + khalf*(16*68);
        outp[g*68 + n0w + t2]          = c0[0];
        outp[g*68 + n0w + t2 + 1]      = c0[1];
        outp[(g+8)*68 + n0w + t2]      = c0[2];
        outp[(g+8)*68 + n0w + t2 + 1]  = c0[3];
        outp[g*68 + n0w + 8 + t2]      = c1[0];
        outp[g*68 + n0w + 8 + t2 + 1]  = c1[1];
        outp[(g+8)*68 + n0w + 8 + t2]  = c1[2];
        outp[(g+8)*68 + n0w + 8 + t2+1]= c1[3];
    }
    __syncthreads();
    for (int i = tid; i < 1024; i += 256) {
        int qi = i >> 6, d = i & 63;
        float o = ((float*)smx)[qi*68 + d] + ((float*)smx)[16*68 + qi*68 + d];
        #pragma unroll
        for (int j = 0; j < Kb; j++) o += pbin[qi*16 + j] * relv[j*64 + d];
        size_t tok = tokbase + n0 + qi;
        __nv_bfloat16 hb = __float2bfloat16_rn(o);
        g_ohi[tok*Dd + h*DHd + d] = hb;
        g_olo[tok*Dd + h*DHd + d] = __float2bfloat16_rn(o - bf2f(hb));
    }
}

// ---------------- bf16x3 mma GEMM, 3-stage cp.async + ldmatrix ----------------
// CTA 64(M)x128(N), BK=32, 256 thr, 8 warps 2x4 (warp 32x32).
#define SSTR 40
#define GSMEM_TOTAL 92160
__global__ __launch_bounds__(256, 2) void gemm_mma_kernel(
    const __nv_bfloat16* __restrict__ Ahi, const __nv_bfloat16* __restrict__ Alo,
    const __nv_bfloat16* __restrict__ Bhi, const __nv_bfloat16* __restrict__ Blo,
    const float* __restrict__ bias, const float* __restrict__ res,
    float* __restrict__ Cf, __nv_bfloat16* __restrict__ Chi, __nv_bfloat16* __restrict__ Clo,
    int Nc, int Kc, int doGelu) {
    extern __shared__ char smx[];
    __nv_bfloat16* sAhi = (__nv_bfloat16*)smx;
    __nv_bfloat16* sAlo = sAhi + 3*64*SSTR;
    __nv_bfloat16* sBhi = sAlo + 3*64*SSTR;
    __nv_bfloat16* sBlo = sBhi + 3*128*SSTR;

    const int tid = threadIdx.x, wid = tid >> 5, lane = tid & 31;
    const int g = lane >> 2, t2 = (lane & 3)*2;
    const int wm = (wid >> 2)*32, wn = (wid & 3)*32;
    const int m0 = blockIdx.y*64, n0 = blockIdx.x*128;

    const int ar = tid >> 2, ac = (tid & 3)*8;
    const int br0 = tid >> 2, bc0 = (tid & 3)*8;
    const int br1 = (tid + 256) >> 2, bc1 = ((tid + 256) & 3)*8;

    const int which = lane >> 3, rowin = lane & 7;
    uint32_t aoff[2], boff[2];
    #pragma unroll
    for (int i = 0; i < 2; i++)
        aoff[i] = ((wm + i*16 + (which & 1)*8 + rowin)*SSTR + (which >> 1)*8)*2;
    #pragma unroll
    for (int p = 0; p < 2; p++)
        boff[p] = ((wn + p*16 + (which >> 1)*8 + rowin)*SSTR + (which & 1)*8)*2;
    const uint32_t uAhi = smem_to_u32(sAhi), uAlo = smem_to_u32(sAlo);
    const uint32_t uBhi = smem_to_u32(sBhi), uBlo = smem_to_u32(sBlo);

    auto issue = [&](int c, int buf) {
        int kc = c*32;
        cpa16(&sAhi[buf*(64*SSTR) + ar*SSTR + ac], Ahi + (size_t)(m0 + ar)*Kc + kc + ac);
        cpa16(&sAlo[buf*(64*SSTR) + ar*SSTR + ac], Alo + (size_t)(m0 + ar)*Kc + kc + ac);
        cpa16(&sBhi[buf*(128*SSTR) + br0*SSTR + bc0], Bhi + (size_t)(n0 + br0)*Kc + kc + bc0);
        cpa16(&sBhi[buf*(128*SSTR) + br1*SSTR + bc1], Bhi + (size_t)(n0 + br1)*Kc + kc + bc1);
        cpa16(&sBlo[buf*(128*SSTR) + br0*SSTR + bc0], Blo + (size_t)(n0 + br0)*Kc + kc + bc0);
        cpa16(&sBlo[buf*(128*SSTR) + br1*SSTR + bc1], Blo + (size_t)(n0 + br1)*Kc + kc + bc1);
    };

    float acc[2][4][4] = {};
    const int nch = Kc >> 5;
    issue(0, 0); CP_COMMIT();
    issue(1, 1); CP_COMMIT();

    for (int c = 0; c < nch; c++) {
        int buf = c % 3;
        if (c + 2 < nch) {
            CP_WAIT(1);
            __syncthreads();
            issue(c + 2, (c + 2) % 3);
            CP_COMMIT();
        } else {
            CP_WAIT(0);
            __syncthreads();
        }
        const uint32_t offA = buf*(64*SSTR*2), offB = buf*(128*SSTR*2);
        #pragma unroll
        for (int ks = 0; ks < 32; ks += 16) {
            uint32_t ah[2][4], al[2][4], bh[8], bl[8];
            #pragma unroll
            for (int i = 0; i < 2; i++) {
                ldm_x4(ah[i], uAhi + offA + aoff[i] + ks*2);
                ldm_x4(al[i], uAlo + offA + aoff[i] + ks*2);
            }
            #pragma unroll
            for (int p = 0; p < 2; p++) {
                ldm_x4(&bh[p*4], uBhi + offB + boff[p] + ks*2);
                ldm_x4(&bl[p*4], uBlo + offB + boff[p] + ks*2);
            }
            #pragma unroll
            for (int i = 0; i < 2; i++)
                #pragma unroll
                for (int j = 0; j < 4; j++) {
                    mma16816(acc[i][j], ah[i], &bh[j*2]);
                    mma16816(acc[i][j], ah[i], &bl[j*2]);
                    mma16816(acc[i][j], al[i], &bh[j*2]);
                }
        }
    }

    #pragma unroll
    for (int i = 0; i < 2; i++) {
        int r0 = m0 + wm + i*16 + g;
        #pragma unroll
        for (int j = 0; j < 4; j++) {
            int col = n0 + wn + j*8 + t2;
            float b0 = bias[col], b1 = bias[col + 1];
            float2 v0 = { acc[i][j][0] + b0, acc[i][j][1] + b1 };
            float2 v1 = { acc[i][j][2] + b0, acc[i][j][3] + b1 };
            if (res) {
                float2 r0v = *(const float2*)&res[(size_t)r0*Nc + col];
                float2 r1v = *(const float2*)&res[(size_t)(r0 + 8)*Nc + col];
                v0.x += r0v.x; v0.y += r0v.y; v1.x += r1v.x; v1.y += r1v.y;
            }
            if (doGelu) {
                v0.x = 0.5f*v0.x*(1.f + erff(v0.x*0.70710678118654752f));
                v0.y = 0.5f*v0.y*(1.f + erff(v0.y*0.70710678118654752f));
                v1.x = 0.5f*v1.x*(1.f + erff(v1.x*0.70710678118654752f));
                v1.y = 0.5f*v1.y*(1.f + erff(v1.y*0.70710678118654752f));
            }
            if (Chi) {
                __nv_bfloat16 h00 = __float2bfloat16_rn(v0.x), h01 = __float2bfloat16_rn(v0.y);
                __nv_bfloat16 h10 = __float2bfloat16_rn(v1.x), h11 = __float2bfloat16_rn(v1.y);
                __nv_bfloat162 hp0(h00, h01), hp1(h10, h11);
                __nv_bfloat162 lp0(__float2bfloat16_rn(v0.x - bf2f(h00)), __float2bfloat16_rn(v0.y - bf2f(h01)));
                __nv_bfloat162 lp1(__float2bfloat16_rn(v1.x - bf2f(h10)), __float2bfloat16_rn(v1.y - bf2f(h11)));
                *(uint32_t*)&Chi[(size_t)r0*Nc + col]       = *(uint32_t*)&hp0;
                *(uint32_t*)&Chi[(size_t)(r0 + 8)*Nc + col] = *(uint32_t*)&hp1;
                *(uint32_t*)&Clo[(size_t)r0*Nc + col]       = *(uint32_t*)&lp0;
                *(uint32_t*)&Clo[(size_t)(r0 + 8)*Nc + col] = *(uint32_t*)&lp1;
            }
            if (Cf) {
                *(float2*)&Cf[(size_t)r0*Nc + col]       = v0;
                *(float2*)&Cf[(size_t)(r0 + 8)*Nc + col] = v1;
            }
        }
    }
}

// ---------------------------------------------------------------------------
extern "C" void kernel_launch(void* const* d_in, const int* in_sizes, int n_in,
                              void* d_out, int out_size) {
    const float* x     = (const float*)d_in[0];
    const float* coord = (const float*)d_in[1];
    const float* ln1_g = (const float*)d_in[2];
    const float* ln1_b = (const float*)d_in[3];
    const float* wq    = (const float*)d_in[4];
    const float* bq    = (const float*)d_in[5];
    const float* wk    = (const float*)d_in[6];
    const float* bk    = (const float*)d_in[7];
    const float* wv    = (const float*)d_in[8];
    const float* bv    = (const float*)d_in[9];
    const float* wo    = (const float*)d_in[10];
    const float* bo    = (const float*)d_in[11];
    const float* rel_k = (const float*)d_in[12];
    const float* rel_v = (const float*)d_in[13];
    const float* ln2_g = (const float*)d_in[14];
    const float* ln2_b = (const float*)d_in[15];
    const float* w1    = (const float*)d_in[16];
    const float* b1    = (const float*)d_in[17];
    const float* w2    = (const float*)d_in[18];
    const float* b2    = (const float*)d_in[19];
    const float* lnf_g = (const float*)d_in[20];
    const float* lnf_b = (const float*)d_in[21];

    float *px, *pbqkv;
    __nv_bfloat16 *pqkvhi, *pqkvlo, *phhi, *phlo, *pohi, *polo, *pfhi, *pflo, *pwhi, *pwlo;
    cudaGetSymbolAddress((void**)&px,     g_x);
    cudaGetSymbolAddress((void**)&pbqkv,  g_bqkv);
    cudaGetSymbolAddress((void**)&pqkvhi, g_qkvhi);
    cudaGetSymbolAddress((void**)&pqkvlo, g_qkvlo);
    cudaGetSymbolAddress((void**)&phhi,   g_hhi);
    cudaGetSymbolAddress((void**)&phlo,   g_hlo);
    cudaGetSymbolAddress((void**)&pohi,   g_ohi);
    cudaGetSymbolAddress((void**)&polo,   g_olo);
    cudaGetSymbolAddress((void**)&pfhi,   g_fhi);
    cudaGetSymbolAddress((void**)&pflo,   g_flo);
    cudaGetSymbolAddress((void**)&pwhi,   g_whi);
    cudaGetSymbolAddress((void**)&pwlo,   g_wlo);

    cudaFuncSetAttribute(gemm_mma_kernel, cudaFuncAttributeMaxDynamicSharedMemorySize, GSMEM_TOTAL);
    cudaFuncSetAttribute(attn_kernel, cudaFuncAttributeMaxDynamicSharedMemorySize, ASMEM_TOTAL);

    // Launch sequence: memcpy(1), setup(2), ln(3), qkv(4), attn(5) <- ncu capture
    cudaMemcpyAsync(px, x, sizeof(float)*TOK*Dd, cudaMemcpyDeviceToDevice);
    setup_all_kernel<<<dim3(16, 16, Ll*6 + 2), dim3(32, 8)>>>(
        wq, wk, wv, wo, w1, w2, bq, bk, bv, coord);

    const dim3 gQKV(12, 32);   // N=1536
    const dim3 gPRJ(4, 32);    // N=512
    const dim3 gFF1(16, 32);   // N=2048

    for (int l = 0; l < Ll; l++) {
        size_t lo = (size_t)l * WL_STRIDE;
        ln_kernel<<<TOK/8, 256>>>(px, ln1_g + l*Dd, ln1_b + l*Dd, phhi, phlo, nullptr);
        gemm_mma_kernel<<<gQKV, 256, GSMEM_TOTAL>>>(
            phhi, phlo, pwhi + lo, pwlo + lo, pbqkv + l*1536, nullptr,
            nullptr, pqkvhi, pqkvlo, 1536, 512, 0);
        attn_kernel<<<dim3(Nn/16, Hh, Bb), 256, ASMEM_TOTAL>>>(
            rel_k + (size_t)l*Kb*DHd, rel_v + (size_t)l*Kb*DHd);
        gemm_mma_kernel<<<gPRJ, 256, GSMEM_TOTAL>>>(
            pohi, polo, pwhi + lo + 786432, pwlo + lo + 786432, bo + l*Dd, px,
            px, nullptr, nullptr, 512, 512, 0);
        ln_kernel<<<TOK/8, 256>>>(px, ln2_g + l*Dd, ln2_b + l*Dd, phhi, phlo, nullptr);
        gemm_mma_kernel<<<gFF1, 256, GSMEM_TOTAL>>>(
            phhi, phlo, pwhi + lo + 1048576, pwlo + lo + 1048576, b1 + l*Mf, nullptr,
            nullptr, pfhi, pflo, 2048, 512, 1);
        gemm_mma_kernel<<<gPRJ, 256, GSMEM_TOTAL>>>(
            pfhi, pflo, pwhi + lo + 2097152, pwlo + lo + 2097152, b2 + l*Dd, px,
            px, nullptr, nullptr, 512, 2048, 0);
    }
    ln_kernel<<<TOK/8, 256>>>(px, lnf_g, lnf_b, nullptr, nullptr, (float*)d_out);
}